// round 2
// baseline (speedup 1.0000x reference)
#include <cuda_runtime.h>
#include <math.h>

#define BATCH 16384
#define DIM   512
#define CLS   1024
#define INV_TAU 10.0f

// ---- scratch (device globals: allocation-free) ----
__device__ float  g_xn[BATCH * DIM];   // normalized input       (32 MB)
__device__ float  g_pn[CLS * DIM];     // normalized prototypes  ( 2 MB)
__device__ float  g_sim[(size_t)BATCH * CLS]; // sim, then e     (64 MB)
__device__ double g_acc[3];            // 0: ||sum_k p_k||^2, 1: sum ||p_k||^2, 2: sum_b e.sim

__global__ void k_init() {
    if (threadIdx.x < 3) g_acc[threadIdx.x] = 0.0;
}

// ---- row L2 normalize, one block (128 thr, float4) per 512-wide row ----
__global__ void k_norm_x(const float* __restrict__ in) {
    int row = blockIdx.x, t = threadIdx.x;
    float4 v = ((const float4*)(in + (size_t)row * DIM))[t];
    float ss = v.x * v.x + v.y * v.y + v.z * v.z + v.w * v.w;
    #pragma unroll
    for (int o = 16; o; o >>= 1) ss += __shfl_xor_sync(0xffffffffu, ss, o);
    __shared__ float w[4];
    if ((t & 31) == 0) w[t >> 5] = ss;
    __syncthreads();
    ss = w[0] + w[1] + w[2] + w[3];
    float inv = 1.0f / fmaxf(sqrtf(ss), 1e-12f);
    v.x *= inv; v.y *= inv; v.z *= inv; v.w *= inv;
    ((float4*)(g_xn + (size_t)row * DIM))[t] = v;
}

__global__ void k_norm_p(const float* __restrict__ in, float* __restrict__ outp) {
    int row = blockIdx.x, t = threadIdx.x;
    float4 v = ((const float4*)(in + (size_t)row * DIM))[t];
    float ss = v.x * v.x + v.y * v.y + v.z * v.z + v.w * v.w;
    #pragma unroll
    for (int o = 16; o; o >>= 1) ss += __shfl_xor_sync(0xffffffffu, ss, o);
    __shared__ float w[4];
    if ((t & 31) == 0) w[t >> 5] = ss;
    __syncthreads();
    ss = w[0] + w[1] + w[2] + w[3];
    float inv = 1.0f / fmaxf(sqrtf(ss), 1e-12f);
    v.x *= inv; v.y *= inv; v.z *= inv; v.w *= inv;
    ((float4*)(g_pn + (size_t)row * DIM))[t] = v;
    ((float4*)(outp + (size_t)row * DIM))[t] = v;
}

// ---- div_loss pieces: per-column sums of p (fp64).  grid 4 x 128 = 512 cols ----
__global__ void k_proto_stats() {
    int c = blockIdx.x * 128 + threadIdx.x;
    double sc = 0.0, sq = 0.0;
    for (int r = 0; r < CLS; r++) {
        float v = g_pn[(size_t)r * DIM + c];
        sc += (double)v;
        sq = fma((double)v, (double)v, sq);
    }
    double s2 = sc * sc;
    #pragma unroll
    for (int o = 16; o; o >>= 1) {
        s2 += __shfl_xor_sync(0xffffffffu, s2, o);
        sq += __shfl_xor_sync(0xffffffffu, sq, o);
    }
    __shared__ double a[4], b[4];
    if ((threadIdx.x & 31) == 0) { a[threadIdx.x >> 5] = s2; b[threadIdx.x >> 5] = sq; }
    __syncthreads();
    if (threadIdx.x == 0) {
        atomicAdd(&g_acc[0], a[0] + a[1] + a[2] + a[3]);
        atomicAdd(&g_acc[1], b[0] + b[1] + b[2] + b[3]);
    }
}

// ---- GEMM: 128x128 block tile, BK=16, 256 threads, 8x8 micro-tile, fma.rn.f32x2 ----
// MODE 0: sim = g_xn[16384,512] @ g_pn[1024,512]^T      (NT)  -> g_sim
// MODE 1: pt  = g_sim[16384,1024] @ g_pn[1024,512]      (NN)  -> Cout
template <int MODE>
__global__ __launch_bounds__(256) void k_gemm(float* __restrict__ Cout) {
    constexpr int Kd = (MODE == 0) ? 512 : 1024;
    constexpr int Nc = (MODE == 0) ? 1024 : 512;
    constexpr int BM = 128, BN = 128, BK = 16;

    const float* __restrict__ A = (MODE == 0) ? g_xn : g_sim;
    const float* __restrict__ B = g_pn;
    float* __restrict__ C = (MODE == 0) ? g_sim : Cout;

    __shared__ float As[BK][BM + 4];
    __shared__ float Bs[BK][BN + 4];

    int tid = threadIdx.x;
    int tx = tid & 15, ty = tid >> 4;
    int m0 = blockIdx.y * BM, n0 = blockIdx.x * BN;

    unsigned long long acc[8][4];
    #pragma unroll
    for (int i = 0; i < 8; i++)
        #pragma unroll
        for (int j = 0; j < 4; j++) acc[i][j] = 0ull;

    for (int k0 = 0; k0 < Kd; k0 += BK) {
        // A tile: 128 rows x 16 k, transposed into As[k][m]
        #pragma unroll
        for (int l = 0; l < 2; l++) {
            int idx = tid + l * 256;
            int r = idx >> 2, kq = (idx & 3) << 2;
            float4 v = *(const float4*)(A + (size_t)(m0 + r) * Kd + k0 + kq);
            As[kq + 0][r] = v.x; As[kq + 1][r] = v.y;
            As[kq + 2][r] = v.z; As[kq + 3][r] = v.w;
        }
        if constexpr (MODE == 0) {
            // B is [N, Kd] row-major: transpose into Bs[k][n]
            #pragma unroll
            for (int l = 0; l < 2; l++) {
                int idx = tid + l * 256;
                int r = idx >> 2, kq = (idx & 3) << 2;
                float4 v = *(const float4*)(B + (size_t)(n0 + r) * Kd + k0 + kq);
                Bs[kq + 0][r] = v.x; Bs[kq + 1][r] = v.y;
                Bs[kq + 2][r] = v.z; Bs[kq + 3][r] = v.w;
            }
        } else {
            // B is [Kd, Nc] row-major: direct vectorized copy into Bs[k][n]
            #pragma unroll
            for (int l = 0; l < 2; l++) {
                int idx = tid + l * 256;
                int r = idx >> 5, c4 = (idx & 31) << 2;
                *(float4*)&Bs[r][c4] =
                    *(const float4*)(B + (size_t)(k0 + r) * Nc + n0 + c4);
            }
        }
        __syncthreads();

        #pragma unroll
        for (int kk = 0; kk < BK; kk++) {
            float a[8];
            *(float4*)&a[0] = *(const float4*)&As[kk][ty * 8];
            *(float4*)&a[4] = *(const float4*)&As[kk][ty * 8 + 4];
            union { float4 f4[2]; unsigned long long u[4]; } bu;
            bu.f4[0] = *(const float4*)&Bs[kk][tx * 8];
            bu.f4[1] = *(const float4*)&Bs[kk][tx * 8 + 4];

            unsigned long long a2[8];
            #pragma unroll
            for (int i = 0; i < 8; i++) {
                unsigned int ab = __float_as_uint(a[i]);
                asm("mov.b64 %0, {%1, %1};" : "=l"(a2[i]) : "r"(ab));
            }
            #pragma unroll
            for (int i = 0; i < 8; i++)
                #pragma unroll
                for (int j = 0; j < 4; j++)
                    asm("fma.rn.f32x2 %0, %1, %2, %0;"
                        : "+l"(acc[i][j]) : "l"(a2[i]), "l"(bu.u[j]));
        }
        __syncthreads();
    }

    #pragma unroll
    for (int i = 0; i < 8; i++) {
        union { unsigned long long u[4]; float4 f4[2]; } r;
        r.u[0] = acc[i][0]; r.u[1] = acc[i][1];
        r.u[2] = acc[i][2]; r.u[3] = acc[i][3];
        float4* dst = (float4*)(C + (size_t)(m0 + ty * 8 + i) * Nc + n0 + tx * 8);
        dst[0] = r.f4[0];
        dst[1] = r.f4[1];
    }
}

// ---- gumbel-softmax row kernel: one block (256 thr) per batch row of 1024 ----
// reads g_sim (sim), writes g_sim (e), accumulates sum_b (e . sim)
__global__ void k_softmax(const float* __restrict__ u) {
    int row = blockIdx.x, t = threadIdx.x;
    size_t base = (size_t)row * CLS;

    float4 s4 = ((const float4*)(g_sim + base))[t];
    float4 u4 = ((const float4*)(u + base))[t];

    float l[4];
    l[0] = (s4.x - logf(-logf(u4.x))) * INV_TAU;
    l[1] = (s4.y - logf(-logf(u4.y))) * INV_TAU;
    l[2] = (s4.z - logf(-logf(u4.z))) * INV_TAU;
    l[3] = (s4.w - logf(-logf(u4.w))) * INV_TAU;

    float mx = fmaxf(fmaxf(l[0], l[1]), fmaxf(l[2], l[3]));
    #pragma unroll
    for (int o = 16; o; o >>= 1) mx = fmaxf(mx, __shfl_xor_sync(0xffffffffu, mx, o));
    __shared__ float red[8];
    __shared__ float red2[8][2];
    if ((t & 31) == 0) red[t >> 5] = mx;
    __syncthreads();
    mx = red[0];
    #pragma unroll
    for (int i = 1; i < 8; i++) mx = fmaxf(mx, red[i]);

    float e[4];
    e[0] = expf(l[0] - mx); e[1] = expf(l[1] - mx);
    e[2] = expf(l[2] - mx); e[3] = expf(l[3] - mx);
    float sum = e[0] + e[1] + e[2] + e[3];
    float dot = e[0] * s4.x + e[1] * s4.y + e[2] * s4.z + e[3] * s4.w;
    #pragma unroll
    for (int o = 16; o; o >>= 1) {
        sum += __shfl_xor_sync(0xffffffffu, sum, o);
        dot += __shfl_xor_sync(0xffffffffu, dot, o);
    }
    if ((t & 31) == 0) { red2[t >> 5][0] = sum; red2[t >> 5][1] = dot; }
    __syncthreads();
    float tsum = 0.f, tdot = 0.f;
    #pragma unroll
    for (int i = 0; i < 8; i++) { tsum += red2[i][0]; tdot += red2[i][1]; }

    float inv = 1.0f / tsum;
    float4 e4 = make_float4(e[0] * inv, e[1] * inv, e[2] * inv, e[3] * inv);
    ((float4*)(g_sim + base))[t] = e4;

    if (t == 0) atomicAdd(&g_acc[2], (double)(tdot * inv));
}

__global__ void k_finalize(float* __restrict__ out_scalars) {
    out_scalars[0] = (float)(1.0 - g_acc[2] / (double)BATCH);  // sim_loss
    out_scalars[1] = (float)(g_acc[0] - g_acc[1]);             // div_loss
}

extern "C" void kernel_launch(void* const* d_in, const int* in_sizes, int n_in,
                              void* d_out, int out_size) {
    const float* input  = (const float*)d_in[0];   // [16384, 512]
    const float* protos = (const float*)d_in[1];   // [1024, 512]
    const float* gu     = (const float*)d_in[2];   // [16384, 1024]
    float* out = (float*)d_out;
    float* out_pt = out;                                          // [16384, 512]
    float* out_p  = out + (size_t)BATCH * DIM;                    // [1024, 512]
    float* out_sc = out + (size_t)BATCH * DIM + (size_t)CLS * DIM;// 2 scalars

    k_init<<<1, 32>>>();
    k_norm_x<<<BATCH, 128>>>(input);
    k_norm_p<<<CLS, 128>>>(protos, out_p);
    k_proto_stats<<<4, 128>>>();
    k_gemm<0><<<dim3(CLS / 128, BATCH / 128), 256>>>(nullptr);   // sim
    k_softmax<<<BATCH, 256>>>(gu);                               // e (in place)
    k_gemm<1><<<dim3(DIM / 128, BATCH / 128), 256>>>(out_pt);    // pt
    k_finalize<<<1, 1>>>(out_sc);
}

// round 3
// speedup vs baseline: 1.0029x; 1.0029x over previous
#include <cuda_runtime.h>
#include <math.h>

#define BATCH 16384
#define DIM   512
#define CLS   1024
#define INV_TAU 10.0f

// ---- scratch (device globals: allocation-free) ----
__device__ float  g_xn[BATCH * DIM];   // normalized input       (32 MB)
__device__ float  g_pn[CLS * DIM];     // normalized prototypes  ( 2 MB)
__device__ float  g_sim[(size_t)BATCH * CLS]; // sim, then e     (64 MB)
__device__ double g_acc[3];            // 0: ||sum_k p_k||^2, 1: sum ||p_k||^2, 2: sum_b e.sim

__global__ void k_init() {
    if (threadIdx.x < 3) g_acc[threadIdx.x] = 0.0;
}

// ---- row L2 normalize, one block (128 thr, float4) per 512-wide row ----
__global__ void k_norm_x(const float* __restrict__ in) {
    int row = blockIdx.x, t = threadIdx.x;
    float4 v = ((const float4*)(in + (size_t)row * DIM))[t];
    float ss = v.x * v.x + v.y * v.y + v.z * v.z + v.w * v.w;
    #pragma unroll
    for (int o = 16; o; o >>= 1) ss += __shfl_xor_sync(0xffffffffu, ss, o);
    __shared__ float w[4];
    if ((t & 31) == 0) w[t >> 5] = ss;
    __syncthreads();
    ss = w[0] + w[1] + w[2] + w[3];
    float inv = 1.0f / fmaxf(sqrtf(ss), 1e-12f);
    v.x *= inv; v.y *= inv; v.z *= inv; v.w *= inv;
    ((float4*)(g_xn + (size_t)row * DIM))[t] = v;
}

__global__ void k_norm_p(const float* __restrict__ in, float* __restrict__ outp) {
    int row = blockIdx.x, t = threadIdx.x;
    float4 v = ((const float4*)(in + (size_t)row * DIM))[t];
    float ss = v.x * v.x + v.y * v.y + v.z * v.z + v.w * v.w;
    #pragma unroll
    for (int o = 16; o; o >>= 1) ss += __shfl_xor_sync(0xffffffffu, ss, o);
    __shared__ float w[4];
    if ((t & 31) == 0) w[t >> 5] = ss;
    __syncthreads();
    ss = w[0] + w[1] + w[2] + w[3];
    float inv = 1.0f / fmaxf(sqrtf(ss), 1e-12f);
    v.x *= inv; v.y *= inv; v.z *= inv; v.w *= inv;
    ((float4*)(g_pn + (size_t)row * DIM))[t] = v;
    ((float4*)(outp + (size_t)row * DIM))[t] = v;
}

// ---- div_loss pieces: per-column sums of p (fp64).  grid 4 x 128 = 512 cols ----
__global__ void k_proto_stats() {
    int c = blockIdx.x * 128 + threadIdx.x;
    double sc = 0.0, sq = 0.0;
    for (int r = 0; r < CLS; r++) {
        float v = g_pn[(size_t)r * DIM + c];
        sc += (double)v;
        sq = fma((double)v, (double)v, sq);
    }
    double s2 = sc * sc;
    #pragma unroll
    for (int o = 16; o; o >>= 1) {
        s2 += __shfl_xor_sync(0xffffffffu, s2, o);
        sq += __shfl_xor_sync(0xffffffffu, sq, o);
    }
    __shared__ double a[4], b[4];
    if ((threadIdx.x & 31) == 0) { a[threadIdx.x >> 5] = s2; b[threadIdx.x >> 5] = sq; }
    __syncthreads();
    if (threadIdx.x == 0) {
        atomicAdd(&g_acc[0], a[0] + a[1] + a[2] + a[3]);
        atomicAdd(&g_acc[1], b[0] + b[1] + b[2] + b[3]);
    }
}

// ---- GEMM: 128x128 block tile, BK=16, 256 threads, 8x8 micro-tile, fma.rn.f32x2 ----
// MODE 0: sim = g_xn[16384,512] @ g_pn[1024,512]^T      (NT)  -> g_sim
// MODE 1: pt  = g_sim[16384,1024] @ g_pn[1024,512]      (NN)  -> Cout
template <int MODE>
__global__ __launch_bounds__(256) void k_gemm(float* __restrict__ Cout) {
    constexpr int Kd = (MODE == 0) ? 512 : 1024;
    constexpr int Nc = (MODE == 0) ? 1024 : 512;
    constexpr int BM = 128, BN = 128, BK = 16;

    const float* __restrict__ A = (MODE == 0) ? g_xn : g_sim;
    const float* __restrict__ B = g_pn;
    float* __restrict__ C = (MODE == 0) ? g_sim : Cout;

    __shared__ float As[BK][BM + 4];
    __shared__ float Bs[BK][BN + 4];

    int tid = threadIdx.x;
    int tx = tid & 15, ty = tid >> 4;
    int m0 = blockIdx.y * BM, n0 = blockIdx.x * BN;

    unsigned long long acc[8][4];
    #pragma unroll
    for (int i = 0; i < 8; i++)
        #pragma unroll
        for (int j = 0; j < 4; j++) acc[i][j] = 0ull;

    for (int k0 = 0; k0 < Kd; k0 += BK) {
        // A tile: 128 rows x 16 k, transposed into As[k][m]
        #pragma unroll
        for (int l = 0; l < 2; l++) {
            int idx = tid + l * 256;
            int r = idx >> 2, kq = (idx & 3) << 2;
            float4 v = *(const float4*)(A + (size_t)(m0 + r) * Kd + k0 + kq);
            As[kq + 0][r] = v.x; As[kq + 1][r] = v.y;
            As[kq + 2][r] = v.z; As[kq + 3][r] = v.w;
        }
        if constexpr (MODE == 0) {
            // B is [N, Kd] row-major: transpose into Bs[k][n]
            #pragma unroll
            for (int l = 0; l < 2; l++) {
                int idx = tid + l * 256;
                int r = idx >> 2, kq = (idx & 3) << 2;
                float4 v = *(const float4*)(B + (size_t)(n0 + r) * Kd + k0 + kq);
                Bs[kq + 0][r] = v.x; Bs[kq + 1][r] = v.y;
                Bs[kq + 2][r] = v.z; Bs[kq + 3][r] = v.w;
            }
        } else {
            // B is [Kd, Nc] row-major: direct vectorized copy into Bs[k][n]
            #pragma unroll
            for (int l = 0; l < 2; l++) {
                int idx = tid + l * 256;
                int r = idx >> 5, c4 = (idx & 31) << 2;
                *(float4*)&Bs[r][c4] =
                    *(const float4*)(B + (size_t)(k0 + r) * Nc + n0 + c4);
            }
        }
        __syncthreads();

        #pragma unroll
        for (int kk = 0; kk < BK; kk++) {
            float a[8];
            *(float4*)&a[0] = *(const float4*)&As[kk][ty * 8];
            *(float4*)&a[4] = *(const float4*)&As[kk][ty * 8 + 4];
            union { float4 f4[2]; unsigned long long u[4]; } bu;
            bu.f4[0] = *(const float4*)&Bs[kk][tx * 8];
            bu.f4[1] = *(const float4*)&Bs[kk][tx * 8 + 4];

            unsigned long long a2[8];
            #pragma unroll
            for (int i = 0; i < 8; i++) {
                unsigned int ab = __float_as_uint(a[i]);
                asm("mov.b64 %0, {%1, %1};" : "=l"(a2[i]) : "r"(ab));
            }
            #pragma unroll
            for (int i = 0; i < 8; i++)
                #pragma unroll
                for (int j = 0; j < 4; j++)
                    asm("fma.rn.f32x2 %0, %1, %2, %0;"
                        : "+l"(acc[i][j]) : "l"(a2[i]), "l"(bu.u[j]));
        }
        __syncthreads();
    }

    #pragma unroll
    for (int i = 0; i < 8; i++) {
        union { unsigned long long u[4]; float4 f4[2]; } r;
        r.u[0] = acc[i][0]; r.u[1] = acc[i][1];
        r.u[2] = acc[i][2]; r.u[3] = acc[i][3];
        float4* dst = (float4*)(C + (size_t)(m0 + ty * 8 + i) * Nc + n0 + tx * 8);
        dst[0] = r.f4[0];
        dst[1] = r.f4[1];
    }
}

// ---- gumbel-softmax row kernel: one block (256 thr) per batch row of 1024 ----
// reads g_sim (sim), writes g_sim (e), accumulates sum_b (e . sim)
__global__ void k_softmax(const float* __restrict__ u) {
    int row = blockIdx.x, t = threadIdx.x;
    size_t base = (size_t)row * CLS;

    float4 s4 = ((const float4*)(g_sim + base))[t];
    float4 u4 = ((const float4*)(u + base))[t];

    float l[4];
    l[0] = (s4.x - logf(-logf(u4.x))) * INV_TAU;
    l[1] = (s4.y - logf(-logf(u4.y))) * INV_TAU;
    l[2] = (s4.z - logf(-logf(u4.z))) * INV_TAU;
    l[3] = (s4.w - logf(-logf(u4.w))) * INV_TAU;

    float mx = fmaxf(fmaxf(l[0], l[1]), fmaxf(l[2], l[3]));
    #pragma unroll
    for (int o = 16; o; o >>= 1) mx = fmaxf(mx, __shfl_xor_sync(0xffffffffu, mx, o));
    __shared__ float red[8];
    __shared__ float red2[8][2];
    if ((t & 31) == 0) red[t >> 5] = mx;
    __syncthreads();
    mx = red[0];
    #pragma unroll
    for (int i = 1; i < 8; i++) mx = fmaxf(mx, red[i]);

    float e[4];
    e[0] = expf(l[0] - mx); e[1] = expf(l[1] - mx);
    e[2] = expf(l[2] - mx); e[3] = expf(l[3] - mx);
    float sum = e[0] + e[1] + e[2] + e[3];
    float dot = e[0] * s4.x + e[1] * s4.y + e[2] * s4.z + e[3] * s4.w;
    #pragma unroll
    for (int o = 16; o; o >>= 1) {
        sum += __shfl_xor_sync(0xffffffffu, sum, o);
        dot += __shfl_xor_sync(0xffffffffu, dot, o);
    }
    if ((t & 31) == 0) { red2[t >> 5][0] = sum; red2[t >> 5][1] = dot; }
    __syncthreads();
    float tsum = 0.f, tdot = 0.f;
    #pragma unroll
    for (int i = 0; i < 8; i++) { tsum += red2[i][0]; tdot += red2[i][1]; }

    float inv = 1.0f / tsum;
    float4 e4 = make_float4(e[0] * inv, e[1] * inv, e[2] * inv, e[3] * inv);
    ((float4*)(g_sim + base))[t] = e4;

    if (t == 0) atomicAdd(&g_acc[2], (double)(tdot * inv));
}

__global__ void k_finalize(float* __restrict__ out_scalars) {
    out_scalars[0] = (float)(1.0 - g_acc[2] / (double)BATCH);  // sim_loss
    out_scalars[1] = (float)(g_acc[0] - g_acc[1]);             // div_loss
}

extern "C" void kernel_launch(void* const* d_in, const int* in_sizes, int n_in,
                              void* d_out, int out_size) {
    const float* input  = (const float*)d_in[0];   // [16384, 512]
    const float* protos = (const float*)d_in[1];   // [1024, 512]
    const float* gu     = (const float*)d_in[2];   // [16384, 1024]
    float* out = (float*)d_out;
    float* out_pt = out;                                          // [16384, 512]
    float* out_p  = out + (size_t)BATCH * DIM;                    // [1024, 512]
    float* out_sc = out + (size_t)BATCH * DIM + (size_t)CLS * DIM;// 2 scalars

    k_init<<<1, 32>>>();
    k_norm_x<<<BATCH, 128>>>(input);
    k_norm_p<<<CLS, 128>>>(protos, out_p);
    k_proto_stats<<<4, 128>>>();
    k_gemm<0><<<dim3(CLS / 128, BATCH / 128), 256>>>(nullptr);   // sim
    k_softmax<<<BATCH, 256>>>(gu);                               // e (in place)
    k_gemm<1><<<dim3(DIM / 128, BATCH / 128), 256>>>(out_pt);    // pt
    k_finalize<<<1, 1>>>(out_sc);
}

// round 5
// speedup vs baseline: 2.1865x; 2.1801x over previous
#include <cuda_runtime.h>
#include <cuda_bf16.h>
#include <cstdint>
#include <math.h>

#define BATCH 16384
#define DIM   512
#define CLS   1024
#define INV_TAU 10.0f

// ============================ scratch (device globals) ============================
__device__ __nv_bfloat16 g_xh[BATCH * DIM];         // normalized x, bf16 hi
__device__ __nv_bfloat16 g_xl[BATCH * DIM];         // normalized x, bf16 lo
__device__ __nv_bfloat16 g_ph[CLS * DIM];           // normalized p hi   [CLS][DIM] (K-major)
__device__ __nv_bfloat16 g_pl[CLS * DIM];
__device__ __nv_bfloat16 g_pth[DIM * CLS];          // p^T hi [DIM][CLS] (K=CLS contiguous)
__device__ __nv_bfloat16 g_ptl[DIM * CLS];
__device__ __nv_bfloat16 g_eh[BATCH * CLS];         // e bf16 hi
__device__ __nv_bfloat16 g_el[BATCH * CLS];
__device__ float  g_sim[(size_t)BATCH * CLS];       // sim fp32 (64 MB)
__device__ double g_colsum[DIM];
__device__ double g_acc[3];                         // 1: sum||p_k||^2, 2: sum_b e.sim

__global__ void k_init() {
    int t = threadIdx.x;
    if (t < DIM) g_colsum[t] = 0.0;
    if (t < 3) g_acc[t] = 0.0;
}

__device__ __forceinline__ void split2(float v, __nv_bfloat16& h, __nv_bfloat16& l) {
    h = __float2bfloat16(v);
    l = __float2bfloat16(v - __bfloat162float(h));
}

// ---- row L2 normalize x -> bf16 hi/lo ----
__global__ void k_norm_x(const float* __restrict__ in) {
    int row = blockIdx.x, t = threadIdx.x;
    float4 v = ((const float4*)(in + (size_t)row * DIM))[t];
    float ss = v.x * v.x + v.y * v.y + v.z * v.z + v.w * v.w;
    #pragma unroll
    for (int o = 16; o; o >>= 1) ss += __shfl_xor_sync(0xffffffffu, ss, o);
    __shared__ float w[4];
    if ((t & 31) == 0) w[t >> 5] = ss;
    __syncthreads();
    ss = w[0] + w[1] + w[2] + w[3];
    float inv = 1.0f / fmaxf(sqrtf(ss), 1e-12f);
    float f[4] = {v.x * inv, v.y * inv, v.z * inv, v.w * inv};
    union { __nv_bfloat16 b[4]; uint2 u; } H, L;
    #pragma unroll
    for (int i = 0; i < 4; i++) split2(f[i], H.b[i], L.b[i]);
    *(uint2*)(g_xh + (size_t)row * DIM + 4 * t) = H.u;
    *(uint2*)(g_xl + (size_t)row * DIM + 4 * t) = L.u;
}

// ---- normalize p -> fp32 output, bf16 hi/lo, transposed hi/lo ----
__global__ void k_norm_p(const float* __restrict__ in, float* __restrict__ outp) {
    int row = blockIdx.x, t = threadIdx.x;
    float4 v = ((const float4*)(in + (size_t)row * DIM))[t];
    float ss = v.x * v.x + v.y * v.y + v.z * v.z + v.w * v.w;
    #pragma unroll
    for (int o = 16; o; o >>= 1) ss += __shfl_xor_sync(0xffffffffu, ss, o);
    __shared__ float w[4];
    if ((t & 31) == 0) w[t >> 5] = ss;
    __syncthreads();
    ss = w[0] + w[1] + w[2] + w[3];
    float inv = 1.0f / fmaxf(sqrtf(ss), 1e-12f);
    float f[4] = {v.x * inv, v.y * inv, v.z * inv, v.w * inv};
    ((float4*)(outp + (size_t)row * DIM))[t] = make_float4(f[0], f[1], f[2], f[3]);
    union { __nv_bfloat16 b[4]; uint2 u; } H, L;
    #pragma unroll
    for (int i = 0; i < 4; i++) split2(f[i], H.b[i], L.b[i]);
    *(uint2*)(g_ph + (size_t)row * DIM + 4 * t) = H.u;
    *(uint2*)(g_pl + (size_t)row * DIM + 4 * t) = L.u;
    #pragma unroll
    for (int i = 0; i < 4; i++) {
        int c = 4 * t + i;
        g_pth[(size_t)c * CLS + row] = H.b[i];
        g_ptl[(size_t)c * CLS + row] = L.b[i];
    }
}

// ---- div_loss stats. grid (4,16) x 128 thr ----
__global__ void k_proto_stats(const float* __restrict__ p) {
    int col = blockIdx.x * 128 + threadIdx.x;
    int r0 = blockIdx.y * 64;
    double sc = 0.0, sq = 0.0;
    #pragma unroll 4
    for (int r = 0; r < 64; r++) {
        float v = p[(size_t)(r0 + r) * DIM + col];
        sc += (double)v;
        sq = fma((double)v, (double)v, sq);
    }
    atomicAdd(&g_colsum[col], sc);
    #pragma unroll
    for (int o = 16; o; o >>= 1) sq += __shfl_xor_sync(0xffffffffu, sq, o);
    if ((threadIdx.x & 31) == 0) atomicAdd(&g_acc[1], sq);
}

// ============================ split-bf16 mma.sync GEMM ============================
// C[M,N] = (Ah+Al)[M,K] * (Bh+Bl)[N,K]^T, fp32 accum, 3 MMA terms (hh, hl, lh).
// MODE 0: sim = xn @ pn^T   (M=16384, N=1024, K=512)  -> g_sim
// MODE 1: pt  = e @ p       (M=16384, N=512,  K=1024) -> Cout   (B = p^T, [DIM][CLS])
#define BM 128
#define BN 128
#define BK 32
#define PAD 40   // row stride in bf16 elems (80 B): conflict-free fragment LDS

#define MMA_BF16(c, a, b) \
    asm volatile("mma.sync.aligned.m16n8k16.row.col.f32.bf16.bf16.f32 " \
        "{%0,%1,%2,%3}, {%4,%5,%6,%7}, {%8,%9}, {%0,%1,%2,%3};" \
        : "+f"((c)[0]), "+f"((c)[1]), "+f"((c)[2]), "+f"((c)[3]) \
        : "r"((a)[0]), "r"((a)[1]), "r"((a)[2]), "r"((a)[3]), \
          "r"((b)[0]), "r"((b)[1]))

template <int MODE>
__global__ __launch_bounds__(256, 1) void k_gemm(float* __restrict__ Cout) {
    constexpr int Kd  = (MODE == 0) ? 512 : 1024;
    constexpr int Nc  = (MODE == 0) ? 1024 : 512;
    constexpr int NCH = Kd / BK;

    const __nv_bfloat16* __restrict__ pAh = (MODE == 0) ? g_xh : g_eh;
    const __nv_bfloat16* __restrict__ pAl = (MODE == 0) ? g_xl : g_el;
    const __nv_bfloat16* __restrict__ pBh = (MODE == 0) ? g_ph : g_pth;
    const __nv_bfloat16* __restrict__ pBl = (MODE == 0) ? g_pl : g_ptl;
    float* __restrict__ C = (MODE == 0) ? g_sim : Cout;

    __shared__ __align__(16) uint16_t sAh[BM * PAD];
    __shared__ __align__(16) uint16_t sAl[BM * PAD];
    __shared__ __align__(16) uint16_t sBh[BN * PAD];
    __shared__ __align__(16) uint16_t sBl[BN * PAD];

    int tid = threadIdx.x, lane = tid & 31, wid = tid >> 5;
    int warp_m = wid & 3, warp_n = wid >> 2;          // 4 x 2 warp grid
    int m0 = blockIdx.y * BM, n0 = blockIdx.x * BN;

    float acc[2][8][4];
    #pragma unroll
    for (int i = 0; i < 2; i++)
        #pragma unroll
        for (int j = 0; j < 8; j++)
            #pragma unroll
            for (int q = 0; q < 4; q++) acc[i][j][q] = 0.0f;

    // staging regs for gmem->smem (2 uint4 per matrix per thread)
    uint4 rAh[2], rAl[2], rBh[2], rBl[2];

    // thread -> (row, k-offset) for loads: idx = tid + l*256; row = idx/4, koff = (idx%4)*8
    #define LDG_CHUNK(ch) do { \
        _Pragma("unroll") \
        for (int l = 0; l < 2; l++) { \
            int idx = tid + l * 256; \
            int r = idx >> 2, ko = (idx & 3) * 8; \
            size_t ga = (size_t)(m0 + r) * Kd + (ch) * BK + ko; \
            size_t gb = (size_t)(n0 + r) * Kd + (ch) * BK + ko; \
            rAh[l] = *(const uint4*)(pAh + ga); \
            rAl[l] = *(const uint4*)(pAl + ga); \
            rBh[l] = *(const uint4*)(pBh + gb); \
            rBl[l] = *(const uint4*)(pBl + gb); \
        } } while (0)

    #define STS_CHUNK() do { \
        _Pragma("unroll") \
        for (int l = 0; l < 2; l++) { \
            int idx = tid + l * 256; \
            int r = idx >> 2, ko = (idx & 3) * 8; \
            int so = r * PAD + ko; \
            *(uint4*)(sAh + so) = rAh[l]; \
            *(uint4*)(sAl + so) = rAl[l]; \
            *(uint4*)(sBh + so) = rBh[l]; \
            *(uint4*)(sBl + so) = rBl[l]; \
        } } while (0)

    LDG_CHUNK(0);

    #pragma unroll 1
    for (int ch = 0; ch < NCH; ch++) {
        STS_CHUNK();
        __syncthreads();
        if (ch + 1 < NCH) LDG_CHUNK(ch + 1);

        #pragma unroll
        for (int kk = 0; kk < 2; kk++) {
            int kb = kk * 16 + (lane & 3) * 2;
            uint32_t ah[2][4], al[2][4], bh[8][2], bl[8][2];
            #pragma unroll
            for (int mt = 0; mt < 2; mt++) {
                int rb = (warp_m * 32 + mt * 16 + (lane >> 2)) * PAD + kb;
                ah[mt][0] = *(const uint32_t*)(sAh + rb);
                ah[mt][1] = *(const uint32_t*)(sAh + rb + 8 * PAD);
                ah[mt][2] = *(const uint32_t*)(sAh + rb + 8);
                ah[mt][3] = *(const uint32_t*)(sAh + rb + 8 * PAD + 8);
                al[mt][0] = *(const uint32_t*)(sAl + rb);
                al[mt][1] = *(const uint32_t*)(sAl + rb + 8 * PAD);
                al[mt][2] = *(const uint32_t*)(sAl + rb + 8);
                al[mt][3] = *(const uint32_t*)(sAl + rb + 8 * PAD + 8);
            }
            #pragma unroll
            for (int nt = 0; nt < 8; nt++) {
                int rb = (warp_n * 64 + nt * 8 + (lane >> 2)) * PAD + kb;
                bh[nt][0] = *(const uint32_t*)(sBh + rb);
                bh[nt][1] = *(const uint32_t*)(sBh + rb + 8);
                bl[nt][0] = *(const uint32_t*)(sBl + rb);
                bl[nt][1] = *(const uint32_t*)(sBl + rb + 8);
            }
            // 3 split terms, dependent MMAs on an accumulator 16 apart
            #pragma unroll
            for (int mt = 0; mt < 2; mt++)
                #pragma unroll
                for (int nt = 0; nt < 8; nt++) MMA_BF16(acc[mt][nt], ah[mt], bh[nt]);
            #pragma unroll
            for (int mt = 0; mt < 2; mt++)
                #pragma unroll
                for (int nt = 0; nt < 8; nt++) MMA_BF16(acc[mt][nt], ah[mt], bl[nt]);
            #pragma unroll
            for (int mt = 0; mt < 2; mt++)
                #pragma unroll
                for (int nt = 0; nt < 8; nt++) MMA_BF16(acc[mt][nt], al[mt], bh[nt]);
        }
        __syncthreads();
    }

    // epilogue: direct float2 stores (each 32B sector fully covered by 4 lanes)
    #pragma unroll
    for (int mt = 0; mt < 2; mt++) {
        int row = m0 + warp_m * 32 + mt * 16 + (lane >> 2);
        #pragma unroll
        for (int nt = 0; nt < 8; nt++) {
            int col = n0 + warp_n * 64 + nt * 8 + (lane & 3) * 2;
            *(float2*)(C + (size_t)row * Nc + col) =
                make_float2(acc[mt][nt][0], acc[mt][nt][1]);
            *(float2*)(C + (size_t)(row + 8) * Nc + col) =
                make_float2(acc[mt][nt][2], acc[mt][nt][3]);
        }
    }
}

// ---- gumbel-softmax: one block (256 thr) per row; e -> bf16 hi/lo ----
__global__ void k_softmax(const float* __restrict__ u) {
    int row = blockIdx.x, t = threadIdx.x;
    size_t base = (size_t)row * CLS;
    float4 s4 = ((const float4*)(g_sim + base))[t];
    float4 u4 = ((const float4*)(u + base))[t];

    float l[4];
    l[0] = (s4.x - logf(-logf(u4.x))) * INV_TAU;
    l[1] = (s4.y - logf(-logf(u4.y))) * INV_TAU;
    l[2] = (s4.z - logf(-logf(u4.z))) * INV_TAU;
    l[3] = (s4.w - logf(-logf(u4.w))) * INV_TAU;

    float mx = fmaxf(fmaxf(l[0], l[1]), fmaxf(l[2], l[3]));
    #pragma unroll
    for (int o = 16; o; o >>= 1) mx = fmaxf(mx, __shfl_xor_sync(0xffffffffu, mx, o));
    __shared__ float red[8];
    __shared__ float red2[8][2];
    if ((t & 31) == 0) red[t >> 5] = mx;
    __syncthreads();
    mx = red[0];
    #pragma unroll
    for (int i = 1; i < 8; i++) mx = fmaxf(mx, red[i]);

    float e[4];
    e[0] = expf(l[0] - mx); e[1] = expf(l[1] - mx);
    e[2] = expf(l[2] - mx); e[3] = expf(l[3] - mx);
    float sum = e[0] + e[1] + e[2] + e[3];
    float dot = e[0] * s4.x + e[1] * s4.y + e[2] * s4.z + e[3] * s4.w;
    #pragma unroll
    for (int o = 16; o; o >>= 1) {
        sum += __shfl_xor_sync(0xffffffffu, sum, o);
        dot += __shfl_xor_sync(0xffffffffu, dot, o);
    }
    if ((t & 31) == 0) { red2[t >> 5][0] = sum; red2[t >> 5][1] = dot; }
    __syncthreads();
    float tsum = 0.f, tdot = 0.f;
    #pragma unroll
    for (int i = 0; i < 8; i++) { tsum += red2[i][0]; tdot += red2[i][1]; }

    float inv = 1.0f / tsum;
    union { __nv_bfloat16 b[4]; uint2 u2; } H, L;
    #pragma unroll
    for (int i = 0; i < 4; i++) split2(e[i] * inv, H.b[i], L.b[i]);
    *(uint2*)(g_eh + base + 4 * t) = H.u2;
    *(uint2*)(g_el + base + 4 * t) = L.u2;

    if (t == 0) atomicAdd(&g_acc[2], (double)(tdot * inv));
}

// ---- finalize: div_loss = ||sum_k p_k||^2 - sum_k ||p_k||^2 ----
__global__ void k_finalize(float* __restrict__ outs) {
    int t = threadIdx.x;                   // 512 threads
    double cs = g_colsum[t];
    double v = cs * cs;
    #pragma unroll
    for (int o = 16; o; o >>= 1) v += __shfl_xor_sync(0xffffffffu, v, o);
    __shared__ double sm[16];
    if ((t & 31) == 0) sm[t >> 5] = v;
    __syncthreads();
    if (t < 32) {
        double x = (t < 16) ? sm[t] : 0.0;
        #pragma unroll
        for (int o = 16; o; o >>= 1) x += __shfl_xor_sync(0xffffffffu, x, o);
        if (t == 0) {
            outs[0] = (float)(1.0 - g_acc[2] / (double)BATCH);  // sim_loss
            outs[1] = (float)(x - g_acc[1]);                    // div_loss
        }
    }
}

extern "C" void kernel_launch(void* const* d_in, const int* in_sizes, int n_in,
                              void* d_out, int out_size) {
    const float* input  = (const float*)d_in[0];   // [16384, 512]
    const float* protos = (const float*)d_in[1];   // [1024, 512]
    const float* gu     = (const float*)d_in[2];   // [16384, 1024]
    float* out = (float*)d_out;
    float* out_pt = out;                                            // [16384, 512]
    float* out_p  = out + (size_t)BATCH * DIM;                      // [1024, 512]
    float* out_sc = out + (size_t)BATCH * DIM + (size_t)CLS * DIM;  // 2 scalars

    k_init<<<1, 512>>>();
    k_norm_x<<<BATCH, 128>>>(input);
    k_norm_p<<<CLS, 128>>>(protos, out_p);
    k_proto_stats<<<dim3(4, 16), 128>>>(out_p);
    k_gemm<0><<<dim3(CLS / BN, BATCH / BM), 256>>>(nullptr);   // sim
    k_softmax<<<BATCH, 256>>>(gu);                             // e (bf16 hi/lo)
    k_gemm<1><<<dim3(DIM / BN, BATCH / BM), 256>>>(out_pt);    // pt
    k_finalize<<<1, 512>>>(out_sc);
}

// round 6
// speedup vs baseline: 2.7359x; 1.2512x over previous
#include <cuda_runtime.h>
#include <cuda_bf16.h>
#include <cstdint>
#include <math.h>

#define BATCH 16384
#define DIM   512
#define CLS   1024
#define INV_TAU 10.0f

// ============================ scratch (device globals) ============================
__device__ __nv_bfloat16 g_xh[BATCH * DIM];         // normalized x, bf16 hi
__device__ __nv_bfloat16 g_xl[BATCH * DIM];         // normalized x, bf16 lo
__device__ __nv_bfloat16 g_ph[CLS * DIM];           // normalized p hi   [CLS][DIM]
__device__ __nv_bfloat16 g_pl[CLS * DIM];
__device__ __nv_bfloat16 g_pth[DIM * CLS];          // p^T hi [DIM][CLS]
__device__ __nv_bfloat16 g_ptl[DIM * CLS];
__device__ __nv_bfloat16 g_eh[BATCH * CLS];         // e bf16 hi
__device__ __nv_bfloat16 g_el[BATCH * CLS];
__device__ float  g_sim[(size_t)BATCH * CLS];       // sim fp32 (64 MB)
__device__ double g_colsum[DIM];
__device__ double g_acc[3];                         // 1: sum||p_k||^2, 2: sum_b e.sim

__global__ void k_init() {
    int t = threadIdx.x;
    if (t < DIM) g_colsum[t] = 0.0;
    if (t < 3) g_acc[t] = 0.0;
}

__device__ __forceinline__ void split2(float v, __nv_bfloat16& h, __nv_bfloat16& l) {
    h = __float2bfloat16(v);
    l = __float2bfloat16(v - __bfloat162float(h));
}

// ---- row L2 normalize x -> bf16 hi/lo ----
__global__ void k_norm_x(const float* __restrict__ in) {
    int row = blockIdx.x, t = threadIdx.x;
    float4 v = ((const float4*)(in + (size_t)row * DIM))[t];
    float ss = v.x * v.x + v.y * v.y + v.z * v.z + v.w * v.w;
    #pragma unroll
    for (int o = 16; o; o >>= 1) ss += __shfl_xor_sync(0xffffffffu, ss, o);
    __shared__ float w[4];
    if ((t & 31) == 0) w[t >> 5] = ss;
    __syncthreads();
    ss = w[0] + w[1] + w[2] + w[3];
    float inv = 1.0f / fmaxf(sqrtf(ss), 1e-12f);
    float f[4] = {v.x * inv, v.y * inv, v.z * inv, v.w * inv};
    union { __nv_bfloat16 b[4]; uint2 u; } H, L;
    #pragma unroll
    for (int i = 0; i < 4; i++) split2(f[i], H.b[i], L.b[i]);
    *(uint2*)(g_xh + (size_t)row * DIM + 4 * t) = H.u;
    *(uint2*)(g_xl + (size_t)row * DIM + 4 * t) = L.u;
}

// ---- normalize p -> fp32 output, bf16 hi/lo, transposed hi/lo ----
__global__ void k_norm_p(const float* __restrict__ in, float* __restrict__ outp) {
    int row = blockIdx.x, t = threadIdx.x;
    float4 v = ((const float4*)(in + (size_t)row * DIM))[t];
    float ss = v.x * v.x + v.y * v.y + v.z * v.z + v.w * v.w;
    #pragma unroll
    for (int o = 16; o; o >>= 1) ss += __shfl_xor_sync(0xffffffffu, ss, o);
    __shared__ float w[4];
    if ((t & 31) == 0) w[t >> 5] = ss;
    __syncthreads();
    ss = w[0] + w[1] + w[2] + w[3];
    float inv = 1.0f / fmaxf(sqrtf(ss), 1e-12f);
    float f[4] = {v.x * inv, v.y * inv, v.z * inv, v.w * inv};
    ((float4*)(outp + (size_t)row * DIM))[t] = make_float4(f[0], f[1], f[2], f[3]);
    union { __nv_bfloat16 b[4]; uint2 u; } H, L;
    #pragma unroll
    for (int i = 0; i < 4; i++) split2(f[i], H.b[i], L.b[i]);
    *(uint2*)(g_ph + (size_t)row * DIM + 4 * t) = H.u;
    *(uint2*)(g_pl + (size_t)row * DIM + 4 * t) = L.u;
    #pragma unroll
    for (int i = 0; i < 4; i++) {
        int c = 4 * t + i;
        g_pth[(size_t)c * CLS + row] = H.b[i];
        g_ptl[(size_t)c * CLS + row] = L.b[i];
    }
}

// ---- div_loss stats. grid (4,64) x 128 thr, 16 rows per block ----
__global__ void k_proto_stats(const float* __restrict__ p) {
    int col = blockIdx.x * 128 + threadIdx.x;
    int r0 = blockIdx.y * 16;
    double sc = 0.0, sq = 0.0;
    #pragma unroll
    for (int r = 0; r < 16; r++) {
        float v = p[(size_t)(r0 + r) * DIM + col];
        sc += (double)v;
        sq = fma((double)v, (double)v, sq);
    }
    atomicAdd(&g_colsum[col], sc);
    #pragma unroll
    for (int o = 16; o; o >>= 1) sq += __shfl_xor_sync(0xffffffffu, sq, o);
    if ((threadIdx.x & 31) == 0) atomicAdd(&g_acc[1], sq);
}

// ============================ split-bf16 mma.sync GEMM (ldmatrix) ============================
// C[M,N] = (Ah+Al)[M,K] * (Bh+Bl)[N,K]^T, fp32 accum, 3 MMA terms (hh, hl, lh).
// MODE 0: sim = xn @ pn^T   (M=16384, N=1024, K=512)  -> g_sim
// MODE 1: pt  = e @ p       (M=16384, N=512,  K=1024) -> Cout   (B = p^T, [DIM][CLS])
#define BM 128
#define BN 128
#define BK 32
#define PAD 40                      // row stride in bf16 (80 B) -> conflict-free LDSM
#define MAT_BYTES (BM * PAD * 2)    // 10240 B per matrix tile
#define GSMEM_SZ (8 * MAT_BYTES)    // 2 buffers x 4 matrices = 81920 B

#define MMA_BF16(c, a, b) \
    asm volatile("mma.sync.aligned.m16n8k16.row.col.f32.bf16.bf16.f32 " \
        "{%0,%1,%2,%3}, {%4,%5,%6,%7}, {%8,%9}, {%0,%1,%2,%3};" \
        : "+f"((c)[0]), "+f"((c)[1]), "+f"((c)[2]), "+f"((c)[3]) \
        : "r"((a)[0]), "r"((a)[1]), "r"((a)[2]), "r"((a)[3]), \
          "r"((b)[0]), "r"((b)[1]))

#define LDSM_X4(r, addr) \
    asm volatile("ldmatrix.sync.aligned.m8n8.x4.shared.b16 {%0,%1,%2,%3}, [%4];" \
        : "=r"((r)[0]), "=r"((r)[1]), "=r"((r)[2]), "=r"((r)[3]) : "r"(addr))

template <int MODE>
__global__ __launch_bounds__(256, 1) void k_gemm(float* __restrict__ Cout) {
    constexpr int Kd  = (MODE == 0) ? 512 : 1024;
    constexpr int Nc  = (MODE == 0) ? 1024 : 512;
    constexpr int NCH = Kd / BK;

    const __nv_bfloat16* __restrict__ pAh = (MODE == 0) ? g_xh : g_eh;
    const __nv_bfloat16* __restrict__ pAl = (MODE == 0) ? g_xl : g_el;
    const __nv_bfloat16* __restrict__ pBh = (MODE == 0) ? g_ph : g_pth;
    const __nv_bfloat16* __restrict__ pBl = (MODE == 0) ? g_pl : g_ptl;
    float* __restrict__ C = (MODE == 0) ? g_sim : Cout;

    extern __shared__ __align__(16) char smem[];
    uint32_t sb = (uint32_t)__cvta_generic_to_shared(smem);
    // buffer b, matrix i (0=Ah,1=Al,2=Bh,3=Bl)
    #define SOFF(b, i) ((b) * 4 * MAT_BYTES + (i) * MAT_BYTES)

    int tid = threadIdx.x, lane = tid & 31, wid = tid >> 5;
    int warp_m = wid & 3, warp_n = wid >> 2;          // 4 x 2 warp grid
    int m0 = blockIdx.y * BM, n0 = blockIdx.x * BN;

    float acc[2][8][4];
    #pragma unroll
    for (int i = 0; i < 2; i++)
        #pragma unroll
        for (int j = 0; j < 8; j++)
            #pragma unroll
            for (int q = 0; q < 4; q++) acc[i][j][q] = 0.0f;

    // lane offsets (bf16 elements) for ldmatrix address generation
    int la = (lane & 15) * PAD + ((lane >> 4) << 3);                       // A-type
    int lb = (((lane >> 4) << 3) + (lane & 7)) * PAD + (((lane >> 3) & 1) << 3); // B-type

    uint4 rAh[2], rAl[2], rBh[2], rBl[2];   // gmem->smem staging

    #define LDG_CHUNK(ch) do { \
        _Pragma("unroll") \
        for (int l = 0; l < 2; l++) { \
            int idx = tid + l * 256; \
            int r = idx >> 2, ko = (idx & 3) * 8; \
            size_t ga = (size_t)(m0 + r) * Kd + (ch) * BK + ko; \
            size_t gb = (size_t)(n0 + r) * Kd + (ch) * BK + ko; \
            rAh[l] = *(const uint4*)(pAh + ga); \
            rAl[l] = *(const uint4*)(pAl + ga); \
            rBh[l] = *(const uint4*)(pBh + gb); \
            rBl[l] = *(const uint4*)(pBl + gb); \
        } } while (0)

    #define STS_CHUNK(b) do { \
        _Pragma("unroll") \
        for (int l = 0; l < 2; l++) { \
            int idx = tid + l * 256; \
            int r = idx >> 2, ko = (idx & 3) * 8; \
            int so = (r * PAD + ko) * 2; \
            *(uint4*)(smem + SOFF(b, 0) + so) = rAh[l]; \
            *(uint4*)(smem + SOFF(b, 1) + so) = rAl[l]; \
            *(uint4*)(smem + SOFF(b, 2) + so) = rBh[l]; \
            *(uint4*)(smem + SOFF(b, 3) + so) = rBl[l]; \
        } } while (0)

    LDG_CHUNK(0);
    STS_CHUNK(0);
    __syncthreads();

    #pragma unroll 1
    for (int ch = 0; ch < NCH; ch++) {
        int b = ch & 1;
        if (ch + 1 < NCH) LDG_CHUNK(ch + 1);

        uint32_t uAh = sb + SOFF(b, 0), uAl = sb + SOFF(b, 1);
        uint32_t uBh = sb + SOFF(b, 2), uBl = sb + SOFF(b, 3);

        #pragma unroll
        for (int kk = 0; kk < 2; kk++) {
            int kb = kk * 16;
            uint32_t ah[2][4], al[2][4], bh[4][4], bl[4][4];
            #pragma unroll
            for (int mt = 0; mt < 2; mt++) {
                uint32_t ao = 2u * ((warp_m * 32 + mt * 16) * PAD + la + kb);
                LDSM_X4(ah[mt], uAh + ao);
                LDSM_X4(al[mt], uAl + ao);
            }
            #pragma unroll
            for (int p = 0; p < 4; p++) {
                uint32_t bo = 2u * ((warp_n * 64 + p * 16) * PAD + lb + kb);
                LDSM_X4(bh[p], uBh + bo);
                LDSM_X4(bl[p], uBl + bo);
            }
            // 3 split terms; each acc tile touched 16 MMAs apart
            #pragma unroll
            for (int mt = 0; mt < 2; mt++)
                #pragma unroll
                for (int nt = 0; nt < 8; nt++)
                    MMA_BF16(acc[mt][nt], ah[mt], &bh[nt >> 1][(nt & 1) * 2]);
            #pragma unroll
            for (int mt = 0; mt < 2; mt++)
                #pragma unroll
                for (int nt = 0; nt < 8; nt++)
                    MMA_BF16(acc[mt][nt], ah[mt], &bl[nt >> 1][(nt & 1) * 2]);
            #pragma unroll
            for (int mt = 0; mt < 2; mt++)
                #pragma unroll
                for (int nt = 0; nt < 8; nt++)
                    MMA_BF16(acc[mt][nt], al[mt], &bh[nt >> 1][(nt & 1) * 2]);
        }

        if (ch + 1 < NCH) {
            STS_CHUNK(b ^ 1);
            __syncthreads();
        }
    }

    // epilogue: direct float2 stores (each 32B sector fully covered by 4 lanes)
    #pragma unroll
    for (int mt = 0; mt < 2; mt++) {
        int row = m0 + warp_m * 32 + mt * 16 + (lane >> 2);
        #pragma unroll
        for (int nt = 0; nt < 8; nt++) {
            int col = n0 + warp_n * 64 + nt * 8 + (lane & 3) * 2;
            *(float2*)(C + (size_t)row * Nc + col) =
                make_float2(acc[mt][nt][0], acc[mt][nt][1]);
            *(float2*)(C + (size_t)(row + 8) * Nc + col) =
                make_float2(acc[mt][nt][2], acc[mt][nt][3]);
        }
    }
    #undef SOFF
}

// ---- gumbel-softmax: one block (256 thr) per row; e -> bf16 hi/lo; fast math ----
__global__ void k_softmax(const float* __restrict__ u) {
    int row = blockIdx.x, t = threadIdx.x;
    size_t base = (size_t)row * CLS;
    float4 s4 = ((const float4*)(g_sim + base))[t];
    float4 u4 = ((const float4*)(u + base))[t];

    float l[4];
    l[0] = (s4.x - __logf(-__logf(u4.x))) * INV_TAU;
    l[1] = (s4.y - __logf(-__logf(u4.y))) * INV_TAU;
    l[2] = (s4.z - __logf(-__logf(u4.z))) * INV_TAU;
    l[3] = (s4.w - __logf(-__logf(u4.w))) * INV_TAU;

    float mx = fmaxf(fmaxf(l[0], l[1]), fmaxf(l[2], l[3]));
    #pragma unroll
    for (int o = 16; o; o >>= 1) mx = fmaxf(mx, __shfl_xor_sync(0xffffffffu, mx, o));
    __shared__ float red[8];
    __shared__ float red2[8][2];
    if ((t & 31) == 0) red[t >> 5] = mx;
    __syncthreads();
    mx = red[0];
    #pragma unroll
    for (int i = 1; i < 8; i++) mx = fmaxf(mx, red[i]);

    float e[4];
    e[0] = __expf(l[0] - mx); e[1] = __expf(l[1] - mx);
    e[2] = __expf(l[2] - mx); e[3] = __expf(l[3] - mx);
    float sum = e[0] + e[1] + e[2] + e[3];
    float dot = e[0] * s4.x + e[1] * s4.y + e[2] * s4.z + e[3] * s4.w;
    #pragma unroll
    for (int o = 16; o; o >>= 1) {
        sum += __shfl_xor_sync(0xffffffffu, sum, o);
        dot += __shfl_xor_sync(0xffffffffu, dot, o);
    }
    if ((t & 31) == 0) { red2[t >> 5][0] = sum; red2[t >> 5][1] = dot; }
    __syncthreads();
    float tsum = 0.f, tdot = 0.f;
    #pragma unroll
    for (int i = 0; i < 8; i++) { tsum += red2[i][0]; tdot += red2[i][1]; }

    float inv = 1.0f / tsum;
    union { __nv_bfloat16 b[4]; uint2 u2; } H, L;
    #pragma unroll
    for (int i = 0; i < 4; i++) split2(e[i] * inv, H.b[i], L.b[i]);
    *(uint2*)(g_eh + base + 4 * t) = H.u2;
    *(uint2*)(g_el + base + 4 * t) = L.u2;

    if (t == 0) atomicAdd(&g_acc[2], (double)(tdot * inv));
}

// ---- finalize: div_loss = ||sum_k p_k||^2 - sum_k ||p_k||^2 ----
__global__ void k_finalize(float* __restrict__ outs) {
    int t = threadIdx.x;                   // 512 threads
    double cs = g_colsum[t];
    double v = cs * cs;
    #pragma unroll
    for (int o = 16; o; o >>= 1) v += __shfl_xor_sync(0xffffffffu, v, o);
    __shared__ double sm[16];
    if ((t & 31) == 0) sm[t >> 5] = v;
    __syncthreads();
    if (t < 32) {
        double x = (t < 16) ? sm[t] : 0.0;
        #pragma unroll
        for (int o = 16; o; o >>= 1) x += __shfl_xor_sync(0xffffffffu, x, o);
        if (t == 0) {
            outs[0] = (float)(1.0 - g_acc[2] / (double)BATCH);  // sim_loss
            outs[1] = (float)(x - g_acc[1]);                    // div_loss
        }
    }
}

extern "C" void kernel_launch(void* const* d_in, const int* in_sizes, int n_in,
                              void* d_out, int out_size) {
    const float* input  = (const float*)d_in[0];   // [16384, 512]
    const float* protos = (const float*)d_in[1];   // [1024, 512]
    const float* gu     = (const float*)d_in[2];   // [16384, 1024]
    float* out = (float*)d_out;
    float* out_pt = out;                                            // [16384, 512]
    float* out_p  = out + (size_t)BATCH * DIM;                      // [1024, 512]
    float* out_sc = out + (size_t)BATCH * DIM + (size_t)CLS * DIM;  // 2 scalars

    cudaFuncSetAttribute(k_gemm<0>, cudaFuncAttributeMaxDynamicSharedMemorySize, GSMEM_SZ);
    cudaFuncSetAttribute(k_gemm<1>, cudaFuncAttributeMaxDynamicSharedMemorySize, GSMEM_SZ);

    k_init<<<1, 512>>>();
    k_norm_x<<<BATCH, 128>>>(input);
    k_norm_p<<<CLS, 128>>>(protos, out_p);
    k_proto_stats<<<dim3(4, 64), 128>>>(out_p);
    k_gemm<0><<<dim3(CLS / BN, BATCH / BM), 256, GSMEM_SZ>>>(nullptr);   // sim
    k_softmax<<<BATCH, 256>>>(gu);                                       // e (bf16 hi/lo)
    k_gemm<1><<<dim3(DIM / BN, BATCH / BM), 256, GSMEM_SZ>>>(out_pt);    // pt
    k_finalize<<<1, 512>>>(out_sc);
}

// round 7
// speedup vs baseline: 2.8270x; 1.0333x over previous
#include <cuda_runtime.h>
#include <cuda_bf16.h>
#include <cstdint>
#include <math.h>

#define BATCH 16384
#define DIM   512
#define CLS   1024
#define INV_TAU 10.0f

// ============================ scratch (device globals) ============================
__device__ __nv_bfloat16 g_xh[BATCH * DIM];         // normalized x, bf16 hi
__device__ __nv_bfloat16 g_xl[BATCH * DIM];         // normalized x, bf16 lo
__device__ __nv_bfloat16 g_ph[CLS * DIM];           // normalized p hi   [CLS][DIM]
__device__ __nv_bfloat16 g_pl[CLS * DIM];
__device__ __nv_bfloat16 g_pth[DIM * CLS];          // p^T hi [DIM][CLS]
__device__ __nv_bfloat16 g_ptl[DIM * CLS];
__device__ __nv_bfloat16 g_eh[BATCH * CLS];         // e bf16 hi
__device__ __nv_bfloat16 g_el[BATCH * CLS];
__device__ float  g_sim[(size_t)BATCH * CLS];       // sim fp32 (64 MB)
__device__ double g_colsum[DIM];
__device__ double g_acc[3];                         // 1: sum||p_k||^2, 2: sum_b e.sim

__global__ void k_init() {
    int t = threadIdx.x;
    if (t < DIM) g_colsum[t] = 0.0;
    if (t < 3) g_acc[t] = 0.0;
}

__device__ __forceinline__ void split2(float v, __nv_bfloat16& h, __nv_bfloat16& l) {
    h = __float2bfloat16(v);
    l = __float2bfloat16(v - __bfloat162float(h));
}

// ---- row L2 normalize x -> bf16 hi/lo ----
__global__ void k_norm_x(const float* __restrict__ in) {
    int row = blockIdx.x, t = threadIdx.x;
    float4 v = ((const float4*)(in + (size_t)row * DIM))[t];
    float ss = v.x * v.x + v.y * v.y + v.z * v.z + v.w * v.w;
    #pragma unroll
    for (int o = 16; o; o >>= 1) ss += __shfl_xor_sync(0xffffffffu, ss, o);
    __shared__ float w[4];
    if ((t & 31) == 0) w[t >> 5] = ss;
    __syncthreads();
    ss = w[0] + w[1] + w[2] + w[3];
    float inv = 1.0f / fmaxf(sqrtf(ss), 1e-12f);
    float f[4] = {v.x * inv, v.y * inv, v.z * inv, v.w * inv};
    union { __nv_bfloat16 b[4]; uint2 u; } H, L;
    #pragma unroll
    for (int i = 0; i < 4; i++) split2(f[i], H.b[i], L.b[i]);
    *(uint2*)(g_xh + (size_t)row * DIM + 4 * t) = H.u;
    *(uint2*)(g_xl + (size_t)row * DIM + 4 * t) = L.u;
}

// ---- normalize p -> fp32 output, bf16 hi/lo, transposed hi/lo ----
__global__ void k_norm_p(const float* __restrict__ in, float* __restrict__ outp) {
    int row = blockIdx.x, t = threadIdx.x;
    float4 v = ((const float4*)(in + (size_t)row * DIM))[t];
    float ss = v.x * v.x + v.y * v.y + v.z * v.z + v.w * v.w;
    #pragma unroll
    for (int o = 16; o; o >>= 1) ss += __shfl_xor_sync(0xffffffffu, ss, o);
    __shared__ float w[4];
    if ((t & 31) == 0) w[t >> 5] = ss;
    __syncthreads();
    ss = w[0] + w[1] + w[2] + w[3];
    float inv = 1.0f / fmaxf(sqrtf(ss), 1e-12f);
    float f[4] = {v.x * inv, v.y * inv, v.z * inv, v.w * inv};
    ((float4*)(outp + (size_t)row * DIM))[t] = make_float4(f[0], f[1], f[2], f[3]);
    union { __nv_bfloat16 b[4]; uint2 u; } H, L;
    #pragma unroll
    for (int i = 0; i < 4; i++) split2(f[i], H.b[i], L.b[i]);
    *(uint2*)(g_ph + (size_t)row * DIM + 4 * t) = H.u;
    *(uint2*)(g_pl + (size_t)row * DIM + 4 * t) = L.u;
    #pragma unroll
    for (int i = 0; i < 4; i++) {
        int c = 4 * t + i;
        g_pth[(size_t)c * CLS + row] = H.b[i];
        g_ptl[(size_t)c * CLS + row] = L.b[i];
    }
}

// ---- div_loss stats. grid (4,64) x 128 thr, 16 rows per block ----
__global__ void k_proto_stats(const float* __restrict__ p) {
    int col = blockIdx.x * 128 + threadIdx.x;
    int r0 = blockIdx.y * 16;
    double sc = 0.0, sq = 0.0;
    #pragma unroll
    for (int r = 0; r < 16; r++) {
        float v = p[(size_t)(r0 + r) * DIM + col];
        sc += (double)v;
        sq = fma((double)v, (double)v, sq);
    }
    atomicAdd(&g_colsum[col], sc);
    #pragma unroll
    for (int o = 16; o; o >>= 1) sq += __shfl_xor_sync(0xffffffffu, sq, o);
    if ((threadIdx.x & 31) == 0) atomicAdd(&g_acc[1], sq);
}

// ============================ split-bf16 mma.sync GEMM (ldmatrix + cp.async) ============================
// C[M,N] = (Ah+Al)[M,K] * (Bh+Bl)[N,K]^T, fp32 accum, 3 MMA terms (hh, hl, lh).
// MODE 0: sim = xn @ pn^T   (M=16384, N=1024, K=512)  -> g_sim
// MODE 1: pt  = e @ p       (M=16384, N=512,  K=1024) -> Cout   (B = p^T, [DIM][CLS])
#define BM 128
#define BN 128
#define BK 32
#define PAD 40                      // row stride in bf16 (80 B) -> conflict-free LDSM
#define MAT_BYTES (BM * PAD * 2)    // 10240 B per matrix tile
#define GSMEM_SZ (8 * MAT_BYTES)    // 2 buffers x 4 matrices = 81920 B

#define MMA_BF16(c, a, b) \
    asm volatile("mma.sync.aligned.m16n8k16.row.col.f32.bf16.bf16.f32 " \
        "{%0,%1,%2,%3}, {%4,%5,%6,%7}, {%8,%9}, {%0,%1,%2,%3};" \
        : "+f"((c)[0]), "+f"((c)[1]), "+f"((c)[2]), "+f"((c)[3]) \
        : "r"((a)[0]), "r"((a)[1]), "r"((a)[2]), "r"((a)[3]), \
          "r"((b)[0]), "r"((b)[1]))

#define LDSM_X4(r, addr) \
    asm volatile("ldmatrix.sync.aligned.m8n8.x4.shared.b16 {%0,%1,%2,%3}, [%4];" \
        : "=r"((r)[0]), "=r"((r)[1]), "=r"((r)[2]), "=r"((r)[3]) : "r"(addr))

#define CP_ASYNC16(dst, src) \
    asm volatile("cp.async.cg.shared.global [%0], [%1], 16;" :: "r"(dst), "l"(src))
#define CP_COMMIT() asm volatile("cp.async.commit_group;" ::: "memory")
#define CP_WAIT(N)  asm volatile("cp.async.wait_group %0;" :: "n"(N) : "memory")

template <int MODE>
__global__ __launch_bounds__(256, 2) void k_gemm(float* __restrict__ Cout) {
    constexpr int Kd  = (MODE == 0) ? 512 : 1024;
    constexpr int Nc  = (MODE == 0) ? 1024 : 512;
    constexpr int NCH = Kd / BK;

    const __nv_bfloat16* __restrict__ pAh = (MODE == 0) ? g_xh : g_eh;
    const __nv_bfloat16* __restrict__ pAl = (MODE == 0) ? g_xl : g_el;
    const __nv_bfloat16* __restrict__ pBh = (MODE == 0) ? g_ph : g_pth;
    const __nv_bfloat16* __restrict__ pBl = (MODE == 0) ? g_pl : g_ptl;
    float* __restrict__ C = (MODE == 0) ? g_sim : Cout;

    extern __shared__ __align__(16) char smem[];
    uint32_t sb = (uint32_t)__cvta_generic_to_shared(smem);
    // buffer b, matrix i (0=Ah,1=Al,2=Bh,3=Bl)
    #define SOFF(b, i) ((b) * 4 * MAT_BYTES + (i) * MAT_BYTES)

    int tid = threadIdx.x, lane = tid & 31, wid = tid >> 5;
    int warp_m = wid & 3, warp_n = wid >> 2;          // 4 x 2 warp grid
    int m0 = blockIdx.y * BM, n0 = blockIdx.x * BN;

    float acc[2][8][4];
    #pragma unroll
    for (int i = 0; i < 2; i++)
        #pragma unroll
        for (int j = 0; j < 8; j++)
            #pragma unroll
            for (int q = 0; q < 4; q++) acc[i][j][q] = 0.0f;

    // lane offsets (bf16 elements) for ldmatrix address generation
    int la = (lane & 15) * PAD + ((lane >> 4) << 3);                       // A-type
    int lb = (((lane >> 4) << 3) + (lane & 7)) * PAD + (((lane >> 3) & 1) << 3); // B-type

    // per-thread copy coords: idx = tid + l*256; row = idx/4, koff = (idx%4)*8
    #define ISSUE_CHUNK(ch, b) do { \
        _Pragma("unroll") \
        for (int l = 0; l < 2; l++) { \
            int idx = tid + l * 256; \
            int r = idx >> 2, ko = (idx & 3) * 8; \
            size_t ga = (size_t)(m0 + r) * Kd + (ch) * BK + ko; \
            size_t gb = (size_t)(n0 + r) * Kd + (ch) * BK + ko; \
            uint32_t so = (uint32_t)((r * PAD + ko) * 2); \
            CP_ASYNC16(sb + SOFF(b, 0) + so, pAh + ga); \
            CP_ASYNC16(sb + SOFF(b, 1) + so, pAl + ga); \
            CP_ASYNC16(sb + SOFF(b, 2) + so, pBh + gb); \
            CP_ASYNC16(sb + SOFF(b, 3) + so, pBl + gb); \
        } \
        CP_COMMIT(); } while (0)

    ISSUE_CHUNK(0, 0);

    #pragma unroll 1
    for (int ch = 0; ch < NCH; ch++) {
        int b = ch & 1;
        if (ch + 1 < NCH) { ISSUE_CHUNK(ch + 1, b ^ 1); CP_WAIT(1); }
        else              { CP_WAIT(0); }
        __syncthreads();                       // chunk-b data visible to all

        uint32_t uAh = sb + SOFF(b, 0), uAl = sb + SOFF(b, 1);
        uint32_t uBh = sb + SOFF(b, 2), uBl = sb + SOFF(b, 3);

        #pragma unroll
        for (int kk = 0; kk < 2; kk++) {
            int kb = kk * 16;
            uint32_t ah[2][4], al[2][4], bh[4][4], bl[4][4];
            #pragma unroll
            for (int mt = 0; mt < 2; mt++) {
                uint32_t ao = 2u * ((warp_m * 32 + mt * 16) * PAD + la + kb);
                LDSM_X4(ah[mt], uAh + ao);
                LDSM_X4(al[mt], uAl + ao);
            }
            #pragma unroll
            for (int p = 0; p < 4; p++) {
                uint32_t bo = 2u * ((warp_n * 64 + p * 16) * PAD + lb + kb);
                LDSM_X4(bh[p], uBh + bo);
                LDSM_X4(bl[p], uBl + bo);
            }
            // 3 split terms; each acc tile touched 16 MMAs apart
            #pragma unroll
            for (int mt = 0; mt < 2; mt++)
                #pragma unroll
                for (int nt = 0; nt < 8; nt++)
                    MMA_BF16(acc[mt][nt], ah[mt], &bh[nt >> 1][(nt & 1) * 2]);
            #pragma unroll
            for (int mt = 0; mt < 2; mt++)
                #pragma unroll
                for (int nt = 0; nt < 8; nt++)
                    MMA_BF16(acc[mt][nt], ah[mt], &bl[nt >> 1][(nt & 1) * 2]);
            #pragma unroll
            for (int mt = 0; mt < 2; mt++)
                #pragma unroll
                for (int nt = 0; nt < 8; nt++)
                    MMA_BF16(acc[mt][nt], al[mt], &bh[nt >> 1][(nt & 1) * 2]);
        }

        if (ch + 1 < NCH) __syncthreads();     // buffer-reuse guard for next issue
    }

    // epilogue: direct float2 stores (each 32B sector fully covered by 4 lanes)
    #pragma unroll
    for (int mt = 0; mt < 2; mt++) {
        int row = m0 + warp_m * 32 + mt * 16 + (lane >> 2);
        #pragma unroll
        for (int nt = 0; nt < 8; nt++) {
            int col = n0 + warp_n * 64 + nt * 8 + (lane & 3) * 2;
            *(float2*)(C + (size_t)row * Nc + col) =
                make_float2(acc[mt][nt][0], acc[mt][nt][1]);
            *(float2*)(C + (size_t)(row + 8) * Nc + col) =
                make_float2(acc[mt][nt][2], acc[mt][nt][3]);
        }
    }
    #undef SOFF
}

// ---- gumbel-softmax: one block (256 thr) per row; e -> bf16 hi/lo; fast math ----
__global__ void k_softmax(const float* __restrict__ u) {
    int row = blockIdx.x, t = threadIdx.x;
    size_t base = (size_t)row * CLS;
    float4 s4 = ((const float4*)(g_sim + base))[t];
    float4 u4 = ((const float4*)(u + base))[t];

    float l[4];
    l[0] = (s4.x - __logf(-__logf(u4.x))) * INV_TAU;
    l[1] = (s4.y - __logf(-__logf(u4.y))) * INV_TAU;
    l[2] = (s4.z - __logf(-__logf(u4.z))) * INV_TAU;
    l[3] = (s4.w - __logf(-__logf(u4.w))) * INV_TAU;

    float mx = fmaxf(fmaxf(l[0], l[1]), fmaxf(l[2], l[3]));
    #pragma unroll
    for (int o = 16; o; o >>= 1) mx = fmaxf(mx, __shfl_xor_sync(0xffffffffu, mx, o));
    __shared__ float red[8];
    __shared__ float red2[8][2];
    if ((t & 31) == 0) red[t >> 5] = mx;
    __syncthreads();
    mx = red[0];
    #pragma unroll
    for (int i = 1; i < 8; i++) mx = fmaxf(mx, red[i]);

    float e[4];
    e[0] = __expf(l[0] - mx); e[1] = __expf(l[1] - mx);
    e[2] = __expf(l[2] - mx); e[3] = __expf(l[3] - mx);
    float sum = e[0] + e[1] + e[2] + e[3];
    float dot = e[0] * s4.x + e[1] * s4.y + e[2] * s4.z + e[3] * s4.w;
    #pragma unroll
    for (int o = 16; o; o >>= 1) {
        sum += __shfl_xor_sync(0xffffffffu, sum, o);
        dot += __shfl_xor_sync(0xffffffffu, dot, o);
    }
    if ((t & 31) == 0) { red2[t >> 5][0] = sum; red2[t >> 5][1] = dot; }
    __syncthreads();
    float tsum = 0.f, tdot = 0.f;
    #pragma unroll
    for (int i = 0; i < 8; i++) { tsum += red2[i][0]; tdot += red2[i][1]; }

    float inv = 1.0f / tsum;
    union { __nv_bfloat16 b[4]; uint2 u2; } H, L;
    #pragma unroll
    for (int i = 0; i < 4; i++) split2(e[i] * inv, H.b[i], L.b[i]);
    *(uint2*)(g_eh + base + 4 * t) = H.u2;
    *(uint2*)(g_el + base + 4 * t) = L.u2;

    if (t == 0) atomicAdd(&g_acc[2], (double)(tdot * inv));
}

// ---- finalize: div_loss = ||sum_k p_k||^2 - sum_k ||p_k||^2 ----
__global__ void k_finalize(float* __restrict__ outs) {
    int t = threadIdx.x;                   // 512 threads
    double cs = g_colsum[t];
    double v = cs * cs;
    #pragma unroll
    for (int o = 16; o; o >>= 1) v += __shfl_xor_sync(0xffffffffu, v, o);
    __shared__ double sm[16];
    if ((t & 31) == 0) sm[t >> 5] = v;
    __syncthreads();
    if (t < 32) {
        double x = (t < 16) ? sm[t] : 0.0;
        #pragma unroll
        for (int o = 16; o; o >>= 1) x += __shfl_xor_sync(0xffffffffu, x, o);
        if (t == 0) {
            outs[0] = (float)(1.0 - g_acc[2] / (double)BATCH);  // sim_loss
            outs[1] = (float)(x - g_acc[1]);                    // div_loss
        }
    }
}

extern "C" void kernel_launch(void* const* d_in, const int* in_sizes, int n_in,
                              void* d_out, int out_size) {
    const float* input  = (const float*)d_in[0];   // [16384, 512]
    const float* protos = (const float*)d_in[1];   // [1024, 512]
    const float* gu     = (const float*)d_in[2];   // [16384, 1024]
    float* out = (float*)d_out;
    float* out_pt = out;                                            // [16384, 512]
    float* out_p  = out + (size_t)BATCH * DIM;                      // [1024, 512]
    float* out_sc = out + (size_t)BATCH * DIM + (size_t)CLS * DIM;  // 2 scalars

    cudaFuncSetAttribute(k_gemm<0>, cudaFuncAttributeMaxDynamicSharedMemorySize, GSMEM_SZ);
    cudaFuncSetAttribute(k_gemm<1>, cudaFuncAttributeMaxDynamicSharedMemorySize, GSMEM_SZ);

    k_init<<<1, 512>>>();
    k_norm_x<<<BATCH, 128>>>(input);
    k_norm_p<<<CLS, 128>>>(protos, out_p);
    k_proto_stats<<<dim3(4, 64), 128>>>(out_p);
    k_gemm<0><<<dim3(CLS / BN, BATCH / BM), 256, GSMEM_SZ>>>(nullptr);   // sim
    k_softmax<<<BATCH, 256>>>(gu);                                       // e (bf16 hi/lo)
    k_gemm<1><<<dim3(DIM / BN, BATCH / BM), 256, GSMEM_SZ>>>(out_pt);    // pt
    k_finalize<<<1, 512>>>(out_sc);
}

// round 8
// speedup vs baseline: 3.0282x; 1.0712x over previous
#include <cuda_runtime.h>
#include <cuda_bf16.h>
#include <cstdint>
#include <math.h>

#define BATCH 16384
#define DIM   512
#define CLS   1024
#define INV_TAU 10.0f

// ============================ scratch (device globals) ============================
__device__ __nv_bfloat16 g_xh[BATCH * DIM];         // normalized x, bf16 hi
__device__ __nv_bfloat16 g_xl[BATCH * DIM];         // normalized x, bf16 lo
__device__ __nv_bfloat16 g_ph[CLS * DIM];           // normalized p hi   [CLS][DIM]
__device__ __nv_bfloat16 g_pl[CLS * DIM];
__device__ __nv_bfloat16 g_pth[DIM * CLS];          // p^T hi [DIM][CLS]
__device__ __nv_bfloat16 g_ptl[DIM * CLS];
__device__ __nv_bfloat16 g_eh[BATCH * CLS];         // e bf16 hi
__device__ __nv_bfloat16 g_el[BATCH * CLS];
__device__ float  g_sim[(size_t)BATCH * CLS];       // sim fp32 (64 MB)
__device__ double g_colsum[DIM];
__device__ double g_acc[3];                         // 1: sum||p_k||^2, 2: sum_b e.sim

__global__ void k_init() {
    int t = threadIdx.x;
    if (t < DIM) g_colsum[t] = 0.0;
    if (t < 3) g_acc[t] = 0.0;
}

__device__ __forceinline__ void split2(float v, __nv_bfloat16& h, __nv_bfloat16& l) {
    h = __float2bfloat16(v);
    l = __float2bfloat16(v - __bfloat162float(h));
}

// ---- row L2 normalize x -> bf16 hi/lo ----
__global__ void k_norm_x(const float* __restrict__ in) {
    int row = blockIdx.x, t = threadIdx.x;
    float4 v = ((const float4*)(in + (size_t)row * DIM))[t];
    float ss = v.x * v.x + v.y * v.y + v.z * v.z + v.w * v.w;
    #pragma unroll
    for (int o = 16; o; o >>= 1) ss += __shfl_xor_sync(0xffffffffu, ss, o);
    __shared__ float w[4];
    if ((t & 31) == 0) w[t >> 5] = ss;
    __syncthreads();
    ss = w[0] + w[1] + w[2] + w[3];
    float inv = 1.0f / fmaxf(sqrtf(ss), 1e-12f);
    float f[4] = {v.x * inv, v.y * inv, v.z * inv, v.w * inv};
    union { __nv_bfloat16 b[4]; uint2 u; } H, L;
    #pragma unroll
    for (int i = 0; i < 4; i++) split2(f[i], H.b[i], L.b[i]);
    *(uint2*)(g_xh + (size_t)row * DIM + 4 * t) = H.u;
    *(uint2*)(g_xl + (size_t)row * DIM + 4 * t) = L.u;
}

// ---- normalize p -> fp32 output, bf16 hi/lo, transposed hi/lo ----
__global__ void k_norm_p(const float* __restrict__ in, float* __restrict__ outp) {
    int row = blockIdx.x, t = threadIdx.x;
    float4 v = ((const float4*)(in + (size_t)row * DIM))[t];
    float ss = v.x * v.x + v.y * v.y + v.z * v.z + v.w * v.w;
    #pragma unroll
    for (int o = 16; o; o >>= 1) ss += __shfl_xor_sync(0xffffffffu, ss, o);
    __shared__ float w[4];
    if ((t & 31) == 0) w[t >> 5] = ss;
    __syncthreads();
    ss = w[0] + w[1] + w[2] + w[3];
    float inv = 1.0f / fmaxf(sqrtf(ss), 1e-12f);
    float f[4] = {v.x * inv, v.y * inv, v.z * inv, v.w * inv};
    ((float4*)(outp + (size_t)row * DIM))[t] = make_float4(f[0], f[1], f[2], f[3]);
    union { __nv_bfloat16 b[4]; uint2 u; } H, L;
    #pragma unroll
    for (int i = 0; i < 4; i++) split2(f[i], H.b[i], L.b[i]);
    *(uint2*)(g_ph + (size_t)row * DIM + 4 * t) = H.u;
    *(uint2*)(g_pl + (size_t)row * DIM + 4 * t) = L.u;
    #pragma unroll
    for (int i = 0; i < 4; i++) {
        int c = 4 * t + i;
        g_pth[(size_t)c * CLS + row] = H.b[i];
        g_ptl[(size_t)c * CLS + row] = L.b[i];
    }
}

// ---- div_loss stats. grid (4,64) x 128 thr, 16 rows per block ----
__global__ void k_proto_stats(const float* __restrict__ p) {
    int col = blockIdx.x * 128 + threadIdx.x;
    int r0 = blockIdx.y * 16;
    double sc = 0.0, sq = 0.0;
    #pragma unroll
    for (int r = 0; r < 16; r++) {
        float v = p[(size_t)(r0 + r) * DIM + col];
        sc += (double)v;
        sq = fma((double)v, (double)v, sq);
    }
    atomicAdd(&g_colsum[col], sc);
    #pragma unroll
    for (int o = 16; o; o >>= 1) sq += __shfl_xor_sync(0xffffffffu, sq, o);
    if ((threadIdx.x & 31) == 0) atomicAdd(&g_acc[1], sq);
}

// ============================ split-bf16 mma.sync GEMM ============================
// 128x128 CTA tile, 4 warps (2x2), warp tile 64x64: 24 MAC per smem byte.
// C[M,N] = (Ah+Al)[M,K] * (Bh+Bl)[N,K]^T, fp32 accum, 3 MMA terms (hh, hl, lh).
// MODE 0: sim = xn @ pn^T   (M=16384, N=1024, K=512)  -> g_sim
// MODE 1: pt  = e @ p       (M=16384, N=512,  K=1024) -> Cout   (B = p^T, [DIM][CLS])
#define BM 128
#define BN 128
#define BK 32
#define NTHR 128
#define PAD 40                      // row stride in bf16 (80 B) -> conflict-free LDSM
#define MAT_BYTES (BM * PAD * 2)    // 10240 B per matrix tile
#define GSMEM_SZ (8 * MAT_BYTES)    // 2 buffers x 4 matrices = 81920 B

#define MMA_BF16(c, a, b) \
    asm volatile("mma.sync.aligned.m16n8k16.row.col.f32.bf16.bf16.f32 " \
        "{%0,%1,%2,%3}, {%4,%5,%6,%7}, {%8,%9}, {%0,%1,%2,%3};" \
        : "+f"((c)[0]), "+f"((c)[1]), "+f"((c)[2]), "+f"((c)[3]) \
        : "r"((a)[0]), "r"((a)[1]), "r"((a)[2]), "r"((a)[3]), \
          "r"((b)[0]), "r"((b)[1]))

#define LDSM_X4(r, addr) \
    asm volatile("ldmatrix.sync.aligned.m8n8.x4.shared.b16 {%0,%1,%2,%3}, [%4];" \
        : "=r"((r)[0]), "=r"((r)[1]), "=r"((r)[2]), "=r"((r)[3]) : "r"(addr))

#define CP_ASYNC16(dst, src) \
    asm volatile("cp.async.cg.shared.global [%0], [%1], 16;" :: "r"(dst), "l"(src))
#define CP_COMMIT() asm volatile("cp.async.commit_group;" ::: "memory")
#define CP_WAIT(N)  asm volatile("cp.async.wait_group %0;" :: "n"(N) : "memory")

template <int MODE>
__global__ __launch_bounds__(NTHR, 2) void k_gemm(float* __restrict__ Cout) {
    constexpr int Kd  = (MODE == 0) ? 512 : 1024;
    constexpr int Nc  = (MODE == 0) ? 1024 : 512;
    constexpr int NCH = Kd / BK;

    const __nv_bfloat16* __restrict__ pAh = (MODE == 0) ? g_xh : g_eh;
    const __nv_bfloat16* __restrict__ pAl = (MODE == 0) ? g_xl : g_el;
    const __nv_bfloat16* __restrict__ pBh = (MODE == 0) ? g_ph : g_pth;
    const __nv_bfloat16* __restrict__ pBl = (MODE == 0) ? g_pl : g_ptl;
    float* __restrict__ C = (MODE == 0) ? g_sim : Cout;

    extern __shared__ __align__(16) char smem[];
    uint32_t sb = (uint32_t)__cvta_generic_to_shared(smem);
    // buffer b, matrix i (0=Ah,1=Al,2=Bh,3=Bl)
    #define SOFF(b, i) ((b) * 4 * MAT_BYTES + (i) * MAT_BYTES)

    int tid = threadIdx.x, lane = tid & 31, wid = tid >> 5;
    int warp_m = wid & 1, warp_n = wid >> 1;          // 2 x 2 warp grid, tile 64x64
    int m0 = blockIdx.y * BM, n0 = blockIdx.x * BN;

    float acc[4][8][4];
    #pragma unroll
    for (int i = 0; i < 4; i++)
        #pragma unroll
        for (int j = 0; j < 8; j++)
            #pragma unroll
            for (int q = 0; q < 4; q++) acc[i][j][q] = 0.0f;

    // lane offsets (bf16 elements) for ldmatrix address generation
    int la = (lane & 15) * PAD + ((lane >> 4) << 3);                       // A-type
    int lb = (((lane >> 4) << 3) + (lane & 7)) * PAD + (((lane >> 3) & 1) << 3); // B-type

    // per-thread copy coords: idx = tid + l*128; row = idx/4, koff = (idx%4)*8
    #define ISSUE_CHUNK(ch, b) do { \
        _Pragma("unroll") \
        for (int l = 0; l < 4; l++) { \
            int idx = tid + l * NTHR; \
            int r = idx >> 2, ko = (idx & 3) * 8; \
            size_t ga = (size_t)(m0 + r) * Kd + (ch) * BK + ko; \
            size_t gb = (size_t)(n0 + r) * Kd + (ch) * BK + ko; \
            uint32_t so = (uint32_t)((r * PAD + ko) * 2); \
            CP_ASYNC16(sb + SOFF(b, 0) + so, pAh + ga); \
            CP_ASYNC16(sb + SOFF(b, 1) + so, pAl + ga); \
            CP_ASYNC16(sb + SOFF(b, 2) + so, pBh + gb); \
            CP_ASYNC16(sb + SOFF(b, 3) + so, pBl + gb); \
        } \
        CP_COMMIT(); } while (0)

    ISSUE_CHUNK(0, 0);

    #pragma unroll 1
    for (int ch = 0; ch < NCH; ch++) {
        int b = ch & 1;
        if (ch + 1 < NCH) { ISSUE_CHUNK(ch + 1, b ^ 1); CP_WAIT(1); }
        else              { CP_WAIT(0); }
        __syncthreads();                       // chunk-b data visible to all

        uint32_t uAh = sb + SOFF(b, 0), uAl = sb + SOFF(b, 1);
        uint32_t uBh = sb + SOFF(b, 2), uBl = sb + SOFF(b, 3);

        #pragma unroll
        for (int kk = 0; kk < 2; kk++) {
            int kb = kk * 16;
            uint32_t ah[4][4], al[4][4], bh[4][4], bl[4][4];
            #pragma unroll
            for (int mt = 0; mt < 4; mt++) {
                uint32_t ao = 2u * ((warp_m * 64 + mt * 16) * PAD + la + kb);
                LDSM_X4(ah[mt], uAh + ao);
                LDSM_X4(al[mt], uAl + ao);
            }
            #pragma unroll
            for (int p = 0; p < 4; p++) {
                uint32_t bo = 2u * ((warp_n * 64 + p * 16) * PAD + lb + kb);
                LDSM_X4(bh[p], uBh + bo);
                LDSM_X4(bl[p], uBl + bo);
            }
            // 3 split terms; each acc tile touched 32 MMAs apart
            #pragma unroll
            for (int mt = 0; mt < 4; mt++)
                #pragma unroll
                for (int nt = 0; nt < 8; nt++)
                    MMA_BF16(acc[mt][nt], ah[mt], &bh[nt >> 1][(nt & 1) * 2]);
            #pragma unroll
            for (int mt = 0; mt < 4; mt++)
                #pragma unroll
                for (int nt = 0; nt < 8; nt++)
                    MMA_BF16(acc[mt][nt], ah[mt], &bl[nt >> 1][(nt & 1) * 2]);
            #pragma unroll
            for (int mt = 0; mt < 4; mt++)
                #pragma unroll
                for (int nt = 0; nt < 8; nt++)
                    MMA_BF16(acc[mt][nt], al[mt], &bh[nt >> 1][(nt & 1) * 2]);
        }

        if (ch + 1 < NCH) __syncthreads();     // buffer-reuse guard for next issue
    }

    // epilogue: direct float2 stores (each 32B sector fully covered by 4 lanes)
    #pragma unroll
    for (int mt = 0; mt < 4; mt++) {
        int row = m0 + warp_m * 64 + mt * 16 + (lane >> 2);
        #pragma unroll
        for (int nt = 0; nt < 8; nt++) {
            int col = n0 + warp_n * 64 + nt * 8 + (lane & 3) * 2;
            *(float2*)(C + (size_t)row * Nc + col) =
                make_float2(acc[mt][nt][0], acc[mt][nt][1]);
            *(float2*)(C + (size_t)(row + 8) * Nc + col) =
                make_float2(acc[mt][nt][2], acc[mt][nt][3]);
        }
    }
    #undef SOFF
}

// ---- gumbel-softmax: one block (256 thr) per row; e -> bf16 hi/lo; fast math ----
__global__ void k_softmax(const float* __restrict__ u) {
    int row = blockIdx.x, t = threadIdx.x;
    size_t base = (size_t)row * CLS;
    float4 s4 = ((const float4*)(g_sim + base))[t];
    float4 u4 = ((const float4*)(u + base))[t];

    float l[4];
    l[0] = (s4.x - __logf(-__logf(u4.x))) * INV_TAU;
    l[1] = (s4.y - __logf(-__logf(u4.y))) * INV_TAU;
    l[2] = (s4.z - __logf(-__logf(u4.z))) * INV_TAU;
    l[3] = (s4.w - __logf(-__logf(u4.w))) * INV_TAU;

    float mx = fmaxf(fmaxf(l[0], l[1]), fmaxf(l[2], l[3]));
    #pragma unroll
    for (int o = 16; o; o >>= 1) mx = fmaxf(mx, __shfl_xor_sync(0xffffffffu, mx, o));
    __shared__ float red[8];
    __shared__ float red2[8][2];
    if ((t & 31) == 0) red[t >> 5] = mx;
    __syncthreads();
    mx = red[0];
    #pragma unroll
    for (int i = 1; i < 8; i++) mx = fmaxf(mx, red[i]);

    float e[4];
    e[0] = __expf(l[0] - mx); e[1] = __expf(l[1] - mx);
    e[2] = __expf(l[2] - mx); e[3] = __expf(l[3] - mx);
    float sum = e[0] + e[1] + e[2] + e[3];
    float dot = e[0] * s4.x + e[1] * s4.y + e[2] * s4.z + e[3] * s4.w;
    #pragma unroll
    for (int o = 16; o; o >>= 1) {
        sum += __shfl_xor_sync(0xffffffffu, sum, o);
        dot += __shfl_xor_sync(0xffffffffu, dot, o);
    }
    if ((t & 31) == 0) { red2[t >> 5][0] = sum; red2[t >> 5][1] = dot; }
    __syncthreads();
    float tsum = 0.f, tdot = 0.f;
    #pragma unroll
    for (int i = 0; i < 8; i++) { tsum += red2[i][0]; tdot += red2[i][1]; }

    float inv = 1.0f / tsum;
    union { __nv_bfloat16 b[4]; uint2 u2; } H, L;
    #pragma unroll
    for (int i = 0; i < 4; i++) split2(e[i] * inv, H.b[i], L.b[i]);
    *(uint2*)(g_eh + base + 4 * t) = H.u2;
    *(uint2*)(g_el + base + 4 * t) = L.u2;

    if (t == 0) atomicAdd(&g_acc[2], (double)(tdot * inv));
}

// ---- finalize: div_loss = ||sum_k p_k||^2 - sum_k ||p_k||^2 ----
__global__ void k_finalize(float* __restrict__ outs) {
    int t = threadIdx.x;                   // 512 threads
    double cs = g_colsum[t];
    double v = cs * cs;
    #pragma unroll
    for (int o = 16; o; o >>= 1) v += __shfl_xor_sync(0xffffffffu, v, o);
    __shared__ double sm[16];
    if ((t & 31) == 0) sm[t >> 5] = v;
    __syncthreads();
    if (t < 32) {
        double x = (t < 16) ? sm[t] : 0.0;
        #pragma unroll
        for (int o = 16; o; o >>= 1) x += __shfl_xor_sync(0xffffffffu, x, o);
        if (t == 0) {
            outs[0] = (float)(1.0 - g_acc[2] / (double)BATCH);  // sim_loss
            outs[1] = (float)(x - g_acc[1]);                    // div_loss
        }
    }
}

extern "C" void kernel_launch(void* const* d_in, const int* in_sizes, int n_in,
                              void* d_out, int out_size) {
    const float* input  = (const float*)d_in[0];   // [16384, 512]
    const float* protos = (const float*)d_in[1];   // [1024, 512]
    const float* gu     = (const float*)d_in[2];   // [16384, 1024]
    float* out = (float*)d_out;
    float* out_pt = out;                                            // [16384, 512]
    float* out_p  = out + (size_t)BATCH * DIM;                      // [1024, 512]
    float* out_sc = out + (size_t)BATCH * DIM + (size_t)CLS * DIM;  // 2 scalars

    cudaFuncSetAttribute(k_gemm<0>, cudaFuncAttributeMaxDynamicSharedMemorySize, GSMEM_SZ);
    cudaFuncSetAttribute(k_gemm<1>, cudaFuncAttributeMaxDynamicSharedMemorySize, GSMEM_SZ);

    k_init<<<1, 512>>>();
    k_norm_x<<<BATCH, 128>>>(input);
    k_norm_p<<<CLS, 128>>>(protos, out_p);
    k_proto_stats<<<dim3(4, 64), 128>>>(out_p);
    k_gemm<0><<<dim3(CLS / BN, BATCH / BM), NTHR, GSMEM_SZ>>>(nullptr);   // sim
    k_softmax<<<BATCH, 256>>>(gu);                                        // e (bf16 hi/lo)
    k_gemm<1><<<dim3(DIM / BN, BATCH / BM), NTHR, GSMEM_SZ>>>(out_pt);    // pt
    k_finalize<<<1, 512>>>(out_sc);
}

// round 9
// speedup vs baseline: 6.3325x; 2.0912x over previous
#include <cuda_runtime.h>
#include <cuda_fp16.h>
#include <cstdint>
#include <math.h>

#define BATCH 16384
#define DIM   512
#define CLS   1024
#define INV_TAU 10.0f

// ============================ scratch (device globals) ============================
__device__ __half g_x16[BATCH * DIM];          // normalized x, fp16
__device__ __half g_p16[CLS * DIM];            // normalized p, fp16  [CLS][DIM]
__device__ __half g_pt16[DIM * CLS];           // p^T fp16 [DIM][CLS]
__device__ __half g_e16[BATCH * CLS];          // e fp16
__device__ float  g_sim[(size_t)BATCH * CLS];  // sim fp32 (64 MB)
__device__ double g_colsum[DIM];
__device__ double g_acc[3];                    // 1: sum||p_k||^2, 2: sum_b e.sim

__global__ void k_init() {
    int t = threadIdx.x;
    if (t < DIM) g_colsum[t] = 0.0;
    if (t < 3) g_acc[t] = 0.0;
}

// ---- row L2 normalize x -> fp16 ----
__global__ void k_norm_x(const float* __restrict__ in) {
    int row = blockIdx.x, t = threadIdx.x;
    float4 v = ((const float4*)(in + (size_t)row * DIM))[t];
    float ss = v.x * v.x + v.y * v.y + v.z * v.z + v.w * v.w;
    #pragma unroll
    for (int o = 16; o; o >>= 1) ss += __shfl_xor_sync(0xffffffffu, ss, o);
    __shared__ float w[4];
    if ((t & 31) == 0) w[t >> 5] = ss;
    __syncthreads();
    ss = w[0] + w[1] + w[2] + w[3];
    float inv = 1.0f / fmaxf(sqrtf(ss), 1e-12f);
    union { __half h[4]; uint2 u; } H;
    H.h[0] = __float2half(v.x * inv); H.h[1] = __float2half(v.y * inv);
    H.h[2] = __float2half(v.z * inv); H.h[3] = __float2half(v.w * inv);
    *(uint2*)(g_x16 + (size_t)row * DIM + 4 * t) = H.u;
}

// ---- normalize p -> fp32 output, fp16, transposed fp16 ----
__global__ void k_norm_p(const float* __restrict__ in, float* __restrict__ outp) {
    int row = blockIdx.x, t = threadIdx.x;
    float4 v = ((const float4*)(in + (size_t)row * DIM))[t];
    float ss = v.x * v.x + v.y * v.y + v.z * v.z + v.w * v.w;
    #pragma unroll
    for (int o = 16; o; o >>= 1) ss += __shfl_xor_sync(0xffffffffu, ss, o);
    __shared__ float w[4];
    if ((t & 31) == 0) w[t >> 5] = ss;
    __syncthreads();
    ss = w[0] + w[1] + w[2] + w[3];
    float inv = 1.0f / fmaxf(sqrtf(ss), 1e-12f);
    float f[4] = {v.x * inv, v.y * inv, v.z * inv, v.w * inv};
    ((float4*)(outp + (size_t)row * DIM))[t] = make_float4(f[0], f[1], f[2], f[3]);
    union { __half h[4]; uint2 u; } H;
    #pragma unroll
    for (int i = 0; i < 4; i++) H.h[i] = __float2half(f[i]);
    *(uint2*)(g_p16 + (size_t)row * DIM + 4 * t) = H.u;
    #pragma unroll
    for (int i = 0; i < 4; i++)
        g_pt16[(size_t)(4 * t + i) * CLS + row] = H.h[i];
}

// ---- div_loss stats. grid (4,64) x 128 thr, 16 rows per block ----
__global__ void k_proto_stats(const float* __restrict__ p) {
    int col = blockIdx.x * 128 + threadIdx.x;
    int r0 = blockIdx.y * 16;
    double sc = 0.0, sq = 0.0;
    #pragma unroll
    for (int r = 0; r < 16; r++) {
        float v = p[(size_t)(r0 + r) * DIM + col];
        sc += (double)v;
        sq = fma((double)v, (double)v, sq);
    }
    atomicAdd(&g_colsum[col], sc);
    #pragma unroll
    for (int o = 16; o; o >>= 1) sq += __shfl_xor_sync(0xffffffffu, sq, o);
    if ((threadIdx.x & 31) == 0) atomicAdd(&g_acc[1], sq);
}

// ============================ fp16 mma.sync GEMM ============================
// 128x128 CTA tile, 4 warps (2x2), warp tile 64x64, BK=64, single term.
// MODE 0: sim = xn @ pn^T   (M=16384, N=1024, K=512)  -> g_sim
// MODE 1: pt  = e @ p       (M=16384, N=512,  K=1024) -> Cout  (B = p^T [DIM][CLS])
#define BM 128
#define BN 128
#define BK 64
#define NTHR 128
#define PADROW 72                    // row stride in halves (144 B): 36 words == 4 mod 32
#define MAT_BYTES (BM * PADROW * 2)  // 18432 B
#define GSMEM_SZ (4 * MAT_BYTES)     // 2 buffers x 2 matrices = 73728 B

#define MMA_F16(c, a, b) \
    asm volatile("mma.sync.aligned.m16n8k16.row.col.f32.f16.f16.f32 " \
        "{%0,%1,%2,%3}, {%4,%5,%6,%7}, {%8,%9}, {%0,%1,%2,%3};" \
        : "+f"((c)[0]), "+f"((c)[1]), "+f"((c)[2]), "+f"((c)[3]) \
        : "r"((a)[0]), "r"((a)[1]), "r"((a)[2]), "r"((a)[3]), \
          "r"((b)[0]), "r"((b)[1]))

#define LDSM_X4(r, addr) \
    asm volatile("ldmatrix.sync.aligned.m8n8.x4.shared.b16 {%0,%1,%2,%3}, [%4];" \
        : "=r"((r)[0]), "=r"((r)[1]), "=r"((r)[2]), "=r"((r)[3]) : "r"(addr))

#define CP_ASYNC16(dst, src) \
    asm volatile("cp.async.cg.shared.global [%0], [%1], 16;" :: "r"(dst), "l"(src))
#define CP_COMMIT() asm volatile("cp.async.commit_group;" ::: "memory")
#define CP_WAIT(N)  asm volatile("cp.async.wait_group %0;" :: "n"(N) : "memory")

template <int MODE>
__global__ __launch_bounds__(NTHR, 2) void k_gemm(float* __restrict__ Cout) {
    constexpr int Kd  = (MODE == 0) ? 512 : 1024;
    constexpr int Nc  = (MODE == 0) ? 1024 : 512;
    constexpr int NCH = Kd / BK;

    const __half* __restrict__ pA = (MODE == 0) ? g_x16 : g_e16;
    const __half* __restrict__ pB = (MODE == 0) ? g_p16 : g_pt16;
    float* __restrict__ C = (MODE == 0) ? g_sim : Cout;

    extern __shared__ __align__(16) char smem[];
    uint32_t sb = (uint32_t)__cvta_generic_to_shared(smem);
    // buffer b, matrix i (0=A, 1=B)
    #define SOFF(b, i) ((b) * 2 * MAT_BYTES + (i) * MAT_BYTES)

    int tid = threadIdx.x, lane = tid & 31, wid = tid >> 5;
    int warp_m = wid & 1, warp_n = wid >> 1;          // 2 x 2 warp grid, tile 64x64
    int m0 = blockIdx.y * BM, n0 = blockIdx.x * BN;

    float acc[4][8][4];
    #pragma unroll
    for (int i = 0; i < 4; i++)
        #pragma unroll
        for (int j = 0; j < 8; j++)
            #pragma unroll
            for (int q = 0; q < 4; q++) acc[i][j][q] = 0.0f;

    // lane offsets (half elements) for ldmatrix address generation
    int la = (lane & 15) * PADROW + ((lane >> 4) << 3);                       // A-type
    int lb = (((lane >> 4) << 3) + (lane & 7)) * PADROW + (((lane >> 3) & 1) << 3); // B-type

    // per-thread copy coords: idx = tid + l*128; row = idx/8, koff = (idx%8)*8
    #define ISSUE_CHUNK(ch, b) do { \
        _Pragma("unroll") \
        for (int l = 0; l < 8; l++) { \
            int idx = tid + l * NTHR; \
            int r = idx >> 3, ko = (idx & 7) * 8; \
            size_t ga = (size_t)(m0 + r) * Kd + (ch) * BK + ko; \
            size_t gb = (size_t)(n0 + r) * Kd + (ch) * BK + ko; \
            uint32_t so = (uint32_t)((r * PADROW + ko) * 2); \
            CP_ASYNC16(sb + SOFF(b, 0) + so, pA + ga); \
            CP_ASYNC16(sb + SOFF(b, 1) + so, pB + gb); \
        } \
        CP_COMMIT(); } while (0)

    ISSUE_CHUNK(0, 0);

    #pragma unroll 1
    for (int ch = 0; ch < NCH; ch++) {
        int b = ch & 1;
        if (ch + 1 < NCH) { ISSUE_CHUNK(ch + 1, b ^ 1); CP_WAIT(1); }
        else              { CP_WAIT(0); }
        __syncthreads();                       // chunk-b data visible to all

        uint32_t uA = sb + SOFF(b, 0), uB = sb + SOFF(b, 1);

        #pragma unroll
        for (int kk = 0; kk < 4; kk++) {
            int kb = kk * 16;
            uint32_t a[4][4], bfr[4][4];
            #pragma unroll
            for (int mt = 0; mt < 4; mt++) {
                uint32_t ao = 2u * ((warp_m * 64 + mt * 16) * PADROW + la + kb);
                LDSM_X4(a[mt], uA + ao);
            }
            #pragma unroll
            for (int p = 0; p < 4; p++) {
                uint32_t bo = 2u * ((warp_n * 64 + p * 16) * PADROW + lb + kb);
                LDSM_X4(bfr[p], uB + bo);
            }
            #pragma unroll
            for (int mt = 0; mt < 4; mt++)
                #pragma unroll
                for (int nt = 0; nt < 8; nt++)
                    MMA_F16(acc[mt][nt], a[mt], &bfr[nt >> 1][(nt & 1) * 2]);
        }

        if (ch + 1 < NCH) __syncthreads();     // buffer-reuse guard for next issue
    }

    // epilogue: direct float2 stores (each 32B sector fully covered by 4 lanes)
    #pragma unroll
    for (int mt = 0; mt < 4; mt++) {
        int row = m0 + warp_m * 64 + mt * 16 + (lane >> 2);
        #pragma unroll
        for (int nt = 0; nt < 8; nt++) {
            int col = n0 + warp_n * 64 + nt * 8 + (lane & 3) * 2;
            *(float2*)(C + (size_t)row * Nc + col) =
                make_float2(acc[mt][nt][0], acc[mt][nt][1]);
            *(float2*)(C + (size_t)(row + 8) * Nc + col) =
                make_float2(acc[mt][nt][2], acc[mt][nt][3]);
        }
    }
    #undef SOFF
}

// ---- gumbel-softmax: one block (256 thr) per row; e -> fp16; fast math ----
__global__ void k_softmax(const float* __restrict__ u) {
    int row = blockIdx.x, t = threadIdx.x;
    size_t base = (size_t)row * CLS;
    float4 s4 = ((const float4*)(g_sim + base))[t];
    float4 u4 = ((const float4*)(u + base))[t];

    float l[4];
    l[0] = (s4.x - __logf(-__logf(u4.x))) * INV_TAU;
    l[1] = (s4.y - __logf(-__logf(u4.y))) * INV_TAU;
    l[2] = (s4.z - __logf(-__logf(u4.z))) * INV_TAU;
    l[3] = (s4.w - __logf(-__logf(u4.w))) * INV_TAU;

    float mx = fmaxf(fmaxf(l[0], l[1]), fmaxf(l[2], l[3]));
    #pragma unroll
    for (int o = 16; o; o >>= 1) mx = fmaxf(mx, __shfl_xor_sync(0xffffffffu, mx, o));
    __shared__ float red[8];
    __shared__ float red2[8][2];
    if ((t & 31) == 0) red[t >> 5] = mx;
    __syncthreads();
    mx = red[0];
    #pragma unroll
    for (int i = 1; i < 8; i++) mx = fmaxf(mx, red[i]);

    float e[4];
    e[0] = __expf(l[0] - mx); e[1] = __expf(l[1] - mx);
    e[2] = __expf(l[2] - mx); e[3] = __expf(l[3] - mx);
    float sum = e[0] + e[1] + e[2] + e[3];
    float dot = e[0] * s4.x + e[1] * s4.y + e[2] * s4.z + e[3] * s4.w;
    #pragma unroll
    for (int o = 16; o; o >>= 1) {
        sum += __shfl_xor_sync(0xffffffffu, sum, o);
        dot += __shfl_xor_sync(0xffffffffu, dot, o);
    }
    if ((t & 31) == 0) { red2[t >> 5][0] = sum; red2[t >> 5][1] = dot; }
    __syncthreads();
    float tsum = 0.f, tdot = 0.f;
    #pragma unroll
    for (int i = 0; i < 8; i++) { tsum += red2[i][0]; tdot += red2[i][1]; }

    float inv = 1.0f / tsum;
    union { __half h[4]; uint2 u2; } H;
    #pragma unroll
    for (int i = 0; i < 4; i++) H.h[i] = __float2half(e[i] * inv);
    *(uint2*)(g_e16 + base + 4 * t) = H.u2;

    if (t == 0) atomicAdd(&g_acc[2], (double)(tdot * inv));
}

// ---- finalize: div_loss = ||sum_k p_k||^2 - sum_k ||p_k||^2 ----
__global__ void k_finalize(float* __restrict__ outs) {
    int t = threadIdx.x;                   // 512 threads
    double cs = g_colsum[t];
    double v = cs * cs;
    #pragma unroll
    for (int o = 16; o; o >>= 1) v += __shfl_xor_sync(0xffffffffu, v, o);
    __shared__ double sm[16];
    if ((t & 31) == 0) sm[t >> 5] = v;
    __syncthreads();
    if (t < 32) {
        double x = (t < 16) ? sm[t] : 0.0;
        #pragma unroll
        for (int o = 16; o; o >>= 1) x += __shfl_xor_sync(0xffffffffu, x, o);
        if (t == 0) {
            outs[0] = (float)(1.0 - g_acc[2] / (double)BATCH);  // sim_loss
            outs[1] = (float)(x - g_acc[1]);                    // div_loss
        }
    }
}

extern "C" void kernel_launch(void* const* d_in, const int* in_sizes, int n_in,
                              void* d_out, int out_size) {
    const float* input  = (const float*)d_in[0];   // [16384, 512]
    const float* protos = (const float*)d_in[1];   // [1024, 512]
    const float* gu     = (const float*)d_in[2];   // [16384, 1024]
    float* out = (float*)d_out;
    float* out_pt = out;                                            // [16384, 512]
    float* out_p  = out + (size_t)BATCH * DIM;                      // [1024, 512]
    float* out_sc = out + (size_t)BATCH * DIM + (size_t)CLS * DIM;  // 2 scalars

    cudaFuncSetAttribute(k_gemm<0>, cudaFuncAttributeMaxDynamicSharedMemorySize, GSMEM_SZ);
    cudaFuncSetAttribute(k_gemm<1>, cudaFuncAttributeMaxDynamicSharedMemorySize, GSMEM_SZ);

    k_init<<<1, 512>>>();
    k_norm_x<<<BATCH, 128>>>(input);
    k_norm_p<<<CLS, 128>>>(protos, out_p);
    k_proto_stats<<<dim3(4, 64), 128>>>(out_p);
    k_gemm<0><<<dim3(CLS / BN, BATCH / BM), NTHR, GSMEM_SZ>>>(nullptr);   // sim
    k_softmax<<<BATCH, 256>>>(gu);                                        // e (fp16)
    k_gemm<1><<<dim3(DIM / BN, BATCH / BM), NTHR, GSMEM_SZ>>>(out_pt);    // pt
    k_finalize<<<1, 512>>>(out_sc);
}